// round 12
// baseline (speedup 1.0000x reference)
#include <cuda_runtime.h>
#include <cuda_fp16.h>
#include <cstdint>

#define N_NODES 100000
#define F_IN    512
#define F_HID   256
#define F_OUT   40
#define E_MAX   3200000

#define SCAN_B  512
#define SCAN_NB ((N_NODES + SCAN_B - 1) / SCAN_B)   // 196

// ---------------- scratch (device globals; no allocation allowed) ----------
__device__ __align__(128) __half g_s1h[(size_t)N_NODES * F_HID];   // 51.2 MB
__device__ __align__(128) __half g_h1h[(size_t)N_NODES * F_HID];   // 51.2 MB
__device__ __align__(128) __half g_s2h[(size_t)N_NODES * F_OUT];   // 8 MB

// W1 pre-packed into mma B-fragment order: [kt(32)][nt(32)][lane(32)][2]
__device__ __align__(16) uint32_t g_w1f[32 * 32 * 32 * 2];          // 256 KB
// W2 pre-packed fragments: [kt(16)][nt(5)][lane(32)][2]
__device__ __align__(16) uint32_t g_w2f[16 * 5 * 32 * 2];           // 10 KB

__device__ int  g_cnt[N_NODES];          // zero at module load; re-zeroed by scan_add
__device__ int  g_off[N_NODES + 1];      // +1 sentinel = E
__device__ int  g_pos[N_NODES];
__device__ int  g_blksum[SCAN_NB];
__device__ __align__(16) int2 g_csr[E_MAX];    // (src, float-bits of w)

// ---------------- fp16 mma helper -------------------------------------------
__device__ __forceinline__ void mma_f16(float* c, const uint32_t* a, const uint32_t* b) {
    asm volatile("mma.sync.aligned.m16n8k16.row.col.f32.f16.f16.f32 "
                 "{%0,%1,%2,%3}, {%4,%5,%6,%7}, {%8,%9}, {%0,%1,%2,%3};"
                 : "+f"(c[0]), "+f"(c[1]), "+f"(c[2]), "+f"(c[3])
                 : "r"(a[0]), "r"(a[1]), "r"(a[2]), "r"(a[3]),
                   "r"(b[0]), "r"(b[1]));
}

// ================ pack W1 (fp32 [512,256]) into fragment order ===============
__global__ void pack_W1(const float* __restrict__ W1) {
    const int idx = blockIdx.x * blockDim.x + threadIdx.x;   // 0..32767
    if (idx >= 32 * 32 * 32) return;
    const int kt = idx >> 10;
    const int rem = idx & 1023;
    const int nt = rem >> 5;
    const int ln = rem & 31;
    const int n = nt * 8 + (ln >> 2);
    const int k = kt * 16 + (ln & 3) * 2;
    const __half2 h0 = __floats2half2_rn(W1[(size_t)k * F_HID + n],
                                         W1[(size_t)(k + 1) * F_HID + n]);
    const __half2 h1 = __floats2half2_rn(W1[(size_t)(k + 8) * F_HID + n],
                                         W1[(size_t)(k + 9) * F_HID + n]);
    g_w1f[idx * 2]     = *(const uint32_t*)&h0;
    g_w1f[idx * 2 + 1] = *(const uint32_t*)&h1;
}

// ================ pack W2 (fp32 [256,40]) into fragment order ================
__global__ void pack_W2(const float* __restrict__ W2) {
    const int idx = blockIdx.x * blockDim.x + threadIdx.x;   // 0..2559
    if (idx >= 16 * 5 * 32) return;
    const int kt = idx / (5 * 32);
    const int rem = idx % (5 * 32);
    const int nt = rem / 32;
    const int ln = rem % 32;
    const int n = nt * 8 + (ln >> 2);
    const int k0 = kt * 16 + (ln & 3) * 2;
    const __half2 h0 = __floats2half2_rn(W2[(size_t)k0 * F_OUT + n],
                                         W2[(size_t)(k0 + 1) * F_OUT + n]);
    const __half2 h1 = __floats2half2_rn(W2[(size_t)(k0 + 8) * F_OUT + n],
                                         W2[(size_t)(k0 + 9) * F_OUT + n]);
    g_w2f[idx * 2]     = *(const uint32_t*)&h0;
    g_w2f[idx * 2 + 1] = *(const uint32_t*)&h1;
}

// ================= gemm1: support1 = x @ W1  (fp16 MMA, fp16 out) ==========
#define G1_BM 128
#define G1_BK 32
#define AS_PAD 36

__global__ __launch_bounds__(256, 1) void gemm1_f16(const float* __restrict__ A, int M) {
    __shared__ __align__(16) uint32_t As[2][8][8][AS_PAD];   // 18.4 KB

    const int tid  = threadIdx.x;
    const int lane = tid & 31;
    const int warp = tid >> 5;
    const int wm = warp & 1;
    const int wn = warp >> 1;
    const int rowBase = blockIdx.x * G1_BM;

    const int ar  = tid >> 1;
    const int aks = tid & 1;
    const int amt = ar >> 4, arr = ar & 15;
    const int b0  = arr >> 3;
    const int l0  = (arr & 7) * 4;

    float acc[4][8][4];
    #pragma unroll
    for (int mt = 0; mt < 4; mt++)
        #pragma unroll
        for (int nt = 0; nt < 8; nt++)
            #pragma unroll
            for (int r = 0; r < 4; r++) acc[mt][nt][r] = 0.f;

    const int arow = rowBase + ar;
    const float* Arow = A + (size_t)arow * F_IN + aks * 16;
    float4 pa[4];

    {
        #pragma unroll
        for (int j = 0; j < 4; j++)
            pa[j] = (arow < M) ? __ldcs((const float4*)(Arow + 4 * j))
                               : make_float4(0.f, 0.f, 0.f, 0.f);
        const float* f = (const float*)pa;
        uint4 lo, hi;
        uint32_t* plo = (uint32_t*)&lo;
        uint32_t* phi = (uint32_t*)&hi;
        #pragma unroll
        for (int p = 0; p < 4; p++) {
            const __half2 a = __floats2half2_rn(f[2 * p],     f[2 * p + 1]);
            const __half2 b = __floats2half2_rn(f[8 + 2 * p], f[9 + 2 * p]);
            plo[p] = *(const uint32_t*)&a;
            phi[p] = *(const uint32_t*)&b;
        }
        *(uint4*)&As[0][amt][aks * 4 + b0][l0]     = lo;
        *(uint4*)&As[0][amt][aks * 4 + b0 + 2][l0] = hi;
    }
    __syncthreads();

    const int NT = F_IN / G1_BK;   // 16
    for (int t = 0; t < NT; t++) {
        const int buf = t & 1;
        if (t + 1 < NT) {
            const float* Anext = Arow + (t + 1) * G1_BK;
            #pragma unroll
            for (int j = 0; j < 4; j++)
                pa[j] = (arow < M) ? __ldcs((const float4*)(Anext + 4 * j))
                                   : make_float4(0.f, 0.f, 0.f, 0.f);
        }

        #pragma unroll
        for (int ks = 0; ks < 2; ks++) {
            const int kt = t * 2 + ks;
            uint32_t bfr[8][2];
            #pragma unroll
            for (int nt = 0; nt < 8; nt++) {
                const uint2 v = __ldg((const uint2*)
                    &g_w1f[(((size_t)kt * 32 + wn * 8 + nt) * 32 + lane) * 2]);
                bfr[nt][0] = v.x; bfr[nt][1] = v.y;
            }
            uint32_t afr[4][4];
            #pragma unroll
            for (int mt = 0; mt < 4; mt++)
                #pragma unroll
                for (int r = 0; r < 4; r++)
                    afr[mt][r] = As[buf][wm * 4 + mt][ks * 4 + r][lane];
            #pragma unroll
            for (int mt = 0; mt < 4; mt++)
                #pragma unroll
                for (int nt = 0; nt < 8; nt++)
                    mma_f16(acc[mt][nt], afr[mt], bfr[nt]);
        }

        if (t + 1 < NT) {
            const int nb = buf ^ 1;
            const float* f = (const float*)pa;
            uint4 lo, hi;
            uint32_t* plo = (uint32_t*)&lo;
            uint32_t* phi = (uint32_t*)&hi;
            #pragma unroll
            for (int p = 0; p < 4; p++) {
                const __half2 a = __floats2half2_rn(f[2 * p],     f[2 * p + 1]);
                const __half2 b = __floats2half2_rn(f[8 + 2 * p], f[9 + 2 * p]);
                plo[p] = *(const uint32_t*)&a;
                phi[p] = *(const uint32_t*)&b;
            }
            *(uint4*)&As[nb][amt][aks * 4 + b0][l0]     = lo;
            *(uint4*)&As[nb][amt][aks * 4 + b0 + 2][l0] = hi;
        }
        __syncthreads();
    }

    #pragma unroll
    for (int mt = 0; mt < 4; mt++) {
        const int row0 = rowBase + wm * 64 + mt * 16 + (lane >> 2);
        #pragma unroll
        for (int nt = 0; nt < 8; nt++) {
            const int col = wn * 64 + nt * 8 + (lane & 3) * 2;
            if (row0 < M)
                *(__half2*)(g_s1h + (size_t)row0 * F_HID + col) =
                    __floats2half2_rn(acc[mt][nt][0], acc[mt][nt][1]);
            if (row0 + 8 < M)
                *(__half2*)(g_s1h + (size_t)(row0 + 8) * F_HID + col) =
                    __floats2half2_rn(acc[mt][nt][2], acc[mt][nt][3]);
        }
    }
}

// ================= CSR build =================================================
__global__ void hist_dst(const int* __restrict__ dst, int E) {
    const int e = blockIdx.x * blockDim.x + threadIdx.x;
    if (e < E) atomicAdd(&g_cnt[__ldcs(dst + e)], 1);
}

__global__ void scan_block() {
    __shared__ int sh[SCAN_B];
    const int t = threadIdx.x;
    const int i = blockIdx.x * SCAN_B + t;
    const int v = (i < N_NODES) ? g_cnt[i] : 0;
    sh[t] = v;
    __syncthreads();
    #pragma unroll
    for (int o = 1; o < SCAN_B; o <<= 1) {
        int x = 0;
        if (t >= o) x = sh[t - o];
        __syncthreads();
        sh[t] += x;
        __syncthreads();
    }
    if (i < N_NODES) g_off[i] = sh[t] - v;
    if (t == SCAN_B - 1) g_blksum[blockIdx.x] = sh[t];
}

__global__ void scan_top() {
    __shared__ int sh[256];
    const int t = threadIdx.x;
    const int v = (t < SCAN_NB) ? g_blksum[t] : 0;
    sh[t] = v;
    __syncthreads();
    #pragma unroll
    for (int o = 1; o < 256; o <<= 1) {
        int x = 0;
        if (t >= o) x = sh[t - o];
        __syncthreads();
        sh[t] += x;
        __syncthreads();
    }
    if (t < SCAN_NB) g_blksum[t] = sh[t] - v;
}

// also re-zeroes g_cnt for the next graph replay and writes the sentinel
__global__ void scan_add(int E) {
    const int i = blockIdx.x * blockDim.x + threadIdx.x;
    if (i < N_NODES) {
        const int o = g_off[i] + g_blksum[i / SCAN_B];
        g_off[i] = o;
        g_pos[i] = o;
        g_cnt[i] = 0;
    }
    if (i == 0) g_off[N_NODES] = E;
}

__global__ void fill_csr(const int* __restrict__ src, const int* __restrict__ dst,
                         const float* __restrict__ ew, int E) {
    const int e = blockIdx.x * blockDim.x + threadIdx.x;
    if (e < E) {
        const int p = atomicAdd(&g_pos[__ldcs(dst + e)], 1);
        __stcs(&g_csr[p], make_int2(__ldcs(src + e), __float_as_int(__ldcs(ew + e))));
    }
}

// === layer-1 gather: 2 warps per node (feature-split), fp16 rows ============
__device__ __forceinline__ void accum4(float* acc, uint2 v, float w) {
    const __half2* h = (const __half2*)&v;
    const float2 f0 = __half22float2(h[0]);
    const float2 f1 = __half22float2(h[1]);
    acc[0] = fmaf(w, f0.x, acc[0]);
    acc[1] = fmaf(w, f0.y, acc[1]);
    acc[2] = fmaf(w, f1.x, acc[2]);
    acc[3] = fmaf(w, f1.y, acc[3]);
}

__global__ __launch_bounds__(256) void gather1(const float* __restrict__ b1) {
    const int gid  = (blockIdx.x * blockDim.x + threadIdx.x) >> 5;
    const int lane = threadIdx.x & 31;
    const int n    = gid >> 1;
    const int half = gid & 1;
    if (n >= N_NODES) return;
    const int beg = g_off[n];
    const int end = g_off[n + 1];
    const int foff = half * 32 + lane;   // uint2 index within the 256-half row

    float acc[4];
    {
        const float4 b = __ldg((const float4*)b1 + foff);
        acc[0] = b.x; acc[1] = b.y; acc[2] = b.z; acc[3] = b.w;
    }

    int e = beg;
    for (; e + 7 < end; e += 8) {
        int2 c[8];
        uint2 v[8];
        #pragma unroll
        for (int i = 0; i < 8; i++) c[i] = __ldcs(&g_csr[e + i]);
        #pragma unroll
        for (int i = 0; i < 8; i++)
            v[i] = __ldg((const uint2*)(g_s1h + (size_t)c[i].x * F_HID) + foff);
        #pragma unroll
        for (int i = 0; i < 8; i++) accum4(acc, v[i], __int_as_float(c[i].y));
    }
    for (; e < end; e++) {
        const int2 c = __ldcs(&g_csr[e]);
        const uint2 v = __ldg((const uint2*)(g_s1h + (size_t)c.x * F_HID) + foff);
        accum4(acc, v, __int_as_float(c.y));
    }

    uint2 o;
    __half2* ph = (__half2*)&o;
    ph[0] = __floats2half2_rn(fmaxf(acc[0], 0.f), fmaxf(acc[1], 0.f));
    ph[1] = __floats2half2_rn(fmaxf(acc[2], 0.f), fmaxf(acc[3], 0.f));
    __stcs((uint2*)(g_h1h + (size_t)n * F_HID) + foff, o);
}

// ====== gemm2: support2 = a1 @ W2 (fp16 mma; fragments from g_w2f) ==========
#define G2_NT 5
__global__ __launch_bounds__(256) void gemm2_mma() {
    const int tid = threadIdx.x;
    const int lane = tid & 31, warp = tid >> 5;
    const int node0 = blockIdx.x * 128 + warp * 16 + (lane >> 2);
    const int node1 = node0 + 8;
    const bool v0 = node0 < N_NODES, v1 = node1 < N_NODES;

    float acc[G2_NT][4];
    #pragma unroll
    for (int nt = 0; nt < G2_NT; nt++)
        #pragma unroll
        for (int r = 0; r < 4; r++) acc[nt][r] = 0.f;

    const __half* r0 = g_h1h + (size_t)node0 * F_HID;
    const __half* r1 = g_h1h + (size_t)node1 * F_HID;

    #pragma unroll
    for (int kt = 0; kt < 16; kt++) {
        const int kof = kt * 16 + (lane & 3) * 2;
        uint32_t a[4];
        a[0] = v0 ? __ldg((const uint32_t*)(r0 + kof))     : 0u;
        a[1] = v1 ? __ldg((const uint32_t*)(r1 + kof))     : 0u;
        a[2] = v0 ? __ldg((const uint32_t*)(r0 + kof + 8)) : 0u;
        a[3] = v1 ? __ldg((const uint32_t*)(r1 + kof + 8)) : 0u;
        #pragma unroll
        for (int nt = 0; nt < G2_NT; nt++) {
            const uint2 bv = __ldg((const uint2*)
                &g_w2f[(((size_t)kt * G2_NT + nt) * 32 + lane) * 2]);
            const uint32_t b[2] = {bv.x, bv.y};
            mma_f16(acc[nt], a, b);
        }
    }

    const int col = (lane & 3) * 2;
    #pragma unroll
    for (int nt = 0; nt < G2_NT; nt++) {
        if (v0)
            *(__half2*)(g_s2h + (size_t)node0 * F_OUT + nt * 8 + col) =
                __floats2half2_rn(acc[nt][0], acc[nt][1]);
        if (v1)
            *(__half2*)(g_s2h + (size_t)node1 * F_OUT + nt * 8 + col) =
                __floats2half2_rn(acc[nt][2], acc[nt][3]);
    }
}

// ========== layer-2 gather fused with log_softmax: warp per node ============
__global__ __launch_bounds__(256) void gather2_softmax(const float* __restrict__ b2,
                                                       float* __restrict__ out) {
    const int n = (blockIdx.x * blockDim.x + threadIdx.x) >> 5;
    const int lane = threadIdx.x & 31;
    if (n >= N_NODES) return;
    const int beg = g_off[n];
    const int end = g_off[n + 1];
    const bool act = lane < (F_OUT / 2);

    float accA = 0.f, accB = 0.f;
    if (act) {
        const float2 b = __ldg((const float2*)b2 + lane);
        accA = b.x; accB = b.y;
    }

    int e = beg;
    for (; e + 1 < end; e += 2) {
        const int2 c0 = __ldcs(&g_csr[e]);
        const int2 c1 = __ldcs(&g_csr[e + 1]);
        if (act) {
            const __half2 v0 = __ldg((const __half2*)(g_s2h + (size_t)c0.x * F_OUT) + lane);
            const __half2 v1 = __ldg((const __half2*)(g_s2h + (size_t)c1.x * F_OUT) + lane);
            const float w0 = __int_as_float(c0.y);
            const float w1 = __int_as_float(c1.y);
            const float2 f0 = __half22float2(v0);
            const float2 f1 = __half22float2(v1);
            accA = fmaf(w0, f0.x, accA); accB = fmaf(w0, f0.y, accB);
            accA = fmaf(w1, f1.x, accA); accB = fmaf(w1, f1.y, accB);
        }
    }
    if (e < end) {
        const int2 c = __ldcs(&g_csr[e]);
        if (act) {
            const __half2 v = __ldg((const __half2*)(g_s2h + (size_t)c.x * F_OUT) + lane);
            const float w = __int_as_float(c.y);
            const float2 f = __half22float2(v);
            accA = fmaf(w, f.x, accA); accB = fmaf(w, f.y, accB);
        }
    }

    const float NEG_INF = __int_as_float(0xff800000);
    float m = act ? fmaxf(accA, accB) : NEG_INF;
    #pragma unroll
    for (int o = 16; o > 0; o >>= 1)
        m = fmaxf(m, __shfl_xor_sync(0xffffffffu, m, o));
    float s = act ? (expf(accA - m) + expf(accB - m)) : 0.f;
    #pragma unroll
    for (int o = 16; o > 0; o >>= 1)
        s += __shfl_xor_sync(0xffffffffu, s, o);
    const float l = m + logf(s);

    if (act)
        *((float2*)(out + (size_t)n * F_OUT) + lane) = make_float2(accA - l, accB - l);
}

// ---------------- launch ----------------------------------------------------
extern "C" void kernel_launch(void* const* d_in, const int* in_sizes, int n_in,
                              void* d_out, int out_size) {
    const float* x   = (const float*)d_in[0];
    const int*   ei  = (const int*)d_in[1];
    const float* ew  = (const float*)d_in[2];
    const float* W1  = (const float*)d_in[3];
    const float* b1  = (const float*)d_in[4];
    const float* W2  = (const float*)d_in[5];
    const float* b2  = (const float*)d_in[6];
    float* out = (float*)d_out;

    const int E = in_sizes[2];
    const int* src = ei;
    const int* dst = ei + E;

    // Fork: CSR build + W2 pack run concurrently with W1 pack + gemm1.
    cudaStream_t s2;
    cudaStreamCreate(&s2);
    cudaEvent_t evFork, evJoin;
    cudaEventCreateWithFlags(&evFork, cudaEventDisableTiming);
    cudaEventCreateWithFlags(&evJoin, cudaEventDisableTiming);

    cudaEventRecord(evFork, 0);
    cudaStreamWaitEvent(s2, evFork, 0);

    // branch A (main stream): pack W1, then support1 = x @ W1
    pack_W1<<<128, 256>>>(W1);
    gemm1_f16<<<(N_NODES + G1_BM - 1) / G1_BM, 256>>>(x, N_NODES);

    // branch B (side stream): W2 pack + CSR build
    {
        const int nb = (N_NODES + 255) / 256;
        const int eb = (E + 255) / 256;
        pack_W2<<<10, 256, 0, s2>>>(W2);
        hist_dst<<<eb, 256, 0, s2>>>(dst, E);
        scan_block<<<SCAN_NB, SCAN_B, 0, s2>>>();
        scan_top<<<1, 256, 0, s2>>>();
        scan_add<<<nb, 256, 0, s2>>>(E);
        fill_csr<<<eb, 256, 0, s2>>>(src, dst, ew, E);
    }

    cudaEventRecord(evJoin, s2);
    cudaStreamWaitEvent(0, evJoin, 0);

    // layer-1 gather (2 warps/node, feature-split) + relu + fp16 store
    gather1<<<(N_NODES * 64 + 255) / 256, 256>>>(b1);
    // support2 = a1 @ W2  (fp16 mma, fragments from gmem)
    gemm2_mma<<<(N_NODES + 127) / 128, 256>>>();
    // out = log_softmax(b2 + gather(ew * support2[src]))
    gather2_softmax<<<(N_NODES * 32 + 255) / 256, 256>>>(b2, out);

    cudaStreamDestroy(s2);
    cudaEventDestroy(evFork);
    cudaEventDestroy(evJoin);
}

// round 13
// speedup vs baseline: 1.1023x; 1.1023x over previous
#include <cuda_runtime.h>
#include <cuda_fp16.h>
#include <cstdint>

#define N_NODES 100000
#define F_IN    512
#define F_HID   256
#define F_OUT   40
#define E_MAX   3200000

#define SCAN_B  512
#define SCAN_NB ((N_NODES + SCAN_B - 1) / SCAN_B)   // 196

// ---------------- scratch (device globals; no allocation allowed) ----------
__device__ __align__(128) __half g_s1h[(size_t)N_NODES * F_HID];   // 51.2 MB
__device__ __align__(128) __half g_h1h[(size_t)N_NODES * F_HID];   // 51.2 MB
__device__ __align__(128) __half g_s2h[(size_t)N_NODES * F_OUT];   // 8 MB

// W1 pre-packed into mma B-fragment order: [kt(32)][nt(32)][lane(32)][2]
__device__ __align__(16) uint32_t g_w1f[32 * 32 * 32 * 2];          // 256 KB
// W2 pre-packed fragments: [kt(16)][nt(5)][lane(32)][2]
__device__ __align__(16) uint32_t g_w2f[16 * 5 * 32 * 2];           // 10 KB

__device__ int  g_cnt[N_NODES];          // zero at module load; re-zeroed by scan_add
__device__ int  g_off[N_NODES + 1];      // +1 sentinel = E
__device__ int  g_pos[N_NODES];
__device__ int  g_blksum[SCAN_NB];
__device__ __align__(16) int2 g_csr[E_MAX];    // (src, float-bits of w)

// ---------------- PDL helpers (no-ops when attr not set) --------------------
__device__ __forceinline__ void gdc_wait() {
    asm volatile("griddepcontrol.wait;" ::: "memory");
}
__device__ __forceinline__ void gdc_launch_dependents() {
    asm volatile("griddepcontrol.launch_dependents;");
}

// ---------------- fp16 mma helper -------------------------------------------
__device__ __forceinline__ void mma_f16(float* c, const uint32_t* a, const uint32_t* b) {
    asm volatile("mma.sync.aligned.m16n8k16.row.col.f32.f16.f16.f32 "
                 "{%0,%1,%2,%3}, {%4,%5,%6,%7}, {%8,%9}, {%0,%1,%2,%3};"
                 : "+f"(c[0]), "+f"(c[1]), "+f"(c[2]), "+f"(c[3])
                 : "r"(a[0]), "r"(a[1]), "r"(a[2]), "r"(a[3]),
                   "r"(b[0]), "r"(b[1]));
}

// ================ pack W1 (fp32 [512,256]) into fragment order ===============
__global__ void pack_W1(const float* __restrict__ W1) {
    const int idx = blockIdx.x * blockDim.x + threadIdx.x;   // 0..32767
    if (idx >= 32 * 32 * 32) return;
    const int kt = idx >> 10;
    const int rem = idx & 1023;
    const int nt = rem >> 5;
    const int ln = rem & 31;
    const int n = nt * 8 + (ln >> 2);
    const int k = kt * 16 + (ln & 3) * 2;
    const __half2 h0 = __floats2half2_rn(W1[(size_t)k * F_HID + n],
                                         W1[(size_t)(k + 1) * F_HID + n]);
    const __half2 h1 = __floats2half2_rn(W1[(size_t)(k + 8) * F_HID + n],
                                         W1[(size_t)(k + 9) * F_HID + n]);
    g_w1f[idx * 2]     = *(const uint32_t*)&h0;
    g_w1f[idx * 2 + 1] = *(const uint32_t*)&h1;
}

// ================ pack W2 (fp32 [256,40]) into fragment order ================
__global__ void pack_W2(const float* __restrict__ W2) {
    const int idx = blockIdx.x * blockDim.x + threadIdx.x;   // 0..2559
    if (idx >= 16 * 5 * 32) return;
    const int kt = idx / (5 * 32);
    const int rem = idx % (5 * 32);
    const int nt = rem / 32;
    const int ln = rem % 32;
    const int n = nt * 8 + (ln >> 2);
    const int k0 = kt * 16 + (ln & 3) * 2;
    const __half2 h0 = __floats2half2_rn(W2[(size_t)k0 * F_OUT + n],
                                         W2[(size_t)(k0 + 1) * F_OUT + n]);
    const __half2 h1 = __floats2half2_rn(W2[(size_t)(k0 + 8) * F_OUT + n],
                                         W2[(size_t)(k0 + 9) * F_OUT + n]);
    g_w2f[idx * 2]     = *(const uint32_t*)&h0;
    g_w2f[idx * 2 + 1] = *(const uint32_t*)&h1;
}

// ================= gemm1: support1 = x @ W1  (fp16 MMA, fp16 out) ==========
#define G1_BM 128
#define G1_BK 32
#define AS_PAD 36

__global__ __launch_bounds__(256, 1) void gemm1_f16(const float* __restrict__ A, int M) {
    __shared__ __align__(16) uint32_t As[2][8][8][AS_PAD];   // 18.4 KB

    const int tid  = threadIdx.x;
    const int lane = tid & 31;
    const int warp = tid >> 5;
    const int wm = warp & 1;
    const int wn = warp >> 1;
    const int rowBase = blockIdx.x * G1_BM;

    const int ar  = tid >> 1;
    const int aks = tid & 1;
    const int amt = ar >> 4, arr = ar & 15;
    const int b0  = arr >> 3;
    const int l0  = (arr & 7) * 4;

    float acc[4][8][4];
    #pragma unroll
    for (int mt = 0; mt < 4; mt++)
        #pragma unroll
        for (int nt = 0; nt < 8; nt++)
            #pragma unroll
            for (int r = 0; r < 4; r++) acc[mt][nt][r] = 0.f;

    const int arow = rowBase + ar;
    const float* Arow = A + (size_t)arow * F_IN + aks * 16;
    float4 pa[4];

    {
        #pragma unroll
        for (int j = 0; j < 4; j++)
            pa[j] = (arow < M) ? __ldcs((const float4*)(Arow + 4 * j))
                               : make_float4(0.f, 0.f, 0.f, 0.f);
        const float* f = (const float*)pa;
        uint4 lo, hi;
        uint32_t* plo = (uint32_t*)&lo;
        uint32_t* phi = (uint32_t*)&hi;
        #pragma unroll
        for (int p = 0; p < 4; p++) {
            const __half2 a = __floats2half2_rn(f[2 * p],     f[2 * p + 1]);
            const __half2 b = __floats2half2_rn(f[8 + 2 * p], f[9 + 2 * p]);
            plo[p] = *(const uint32_t*)&a;
            phi[p] = *(const uint32_t*)&b;
        }
        *(uint4*)&As[0][amt][aks * 4 + b0][l0]     = lo;
        *(uint4*)&As[0][amt][aks * 4 + b0 + 2][l0] = hi;
    }
    __syncthreads();

    const int NT = F_IN / G1_BK;   // 16
    for (int t = 0; t < NT; t++) {
        const int buf = t & 1;
        if (t + 1 < NT) {
            const float* Anext = Arow + (t + 1) * G1_BK;
            #pragma unroll
            for (int j = 0; j < 4; j++)
                pa[j] = (arow < M) ? __ldcs((const float4*)(Anext + 4 * j))
                                   : make_float4(0.f, 0.f, 0.f, 0.f);
        }

        #pragma unroll
        for (int ks = 0; ks < 2; ks++) {
            const int kt = t * 2 + ks;
            uint32_t bfr[8][2];
            #pragma unroll
            for (int nt = 0; nt < 8; nt++) {
                const uint2 v = __ldg((const uint2*)
                    &g_w1f[(((size_t)kt * 32 + wn * 8 + nt) * 32 + lane) * 2]);
                bfr[nt][0] = v.x; bfr[nt][1] = v.y;
            }
            uint32_t afr[4][4];
            #pragma unroll
            for (int mt = 0; mt < 4; mt++)
                #pragma unroll
                for (int r = 0; r < 4; r++)
                    afr[mt][r] = As[buf][wm * 4 + mt][ks * 4 + r][lane];
            #pragma unroll
            for (int mt = 0; mt < 4; mt++)
                #pragma unroll
                for (int nt = 0; nt < 8; nt++)
                    mma_f16(acc[mt][nt], afr[mt], bfr[nt]);
        }

        if (t + 1 < NT) {
            const int nb = buf ^ 1;
            const float* f = (const float*)pa;
            uint4 lo, hi;
            uint32_t* plo = (uint32_t*)&lo;
            uint32_t* phi = (uint32_t*)&hi;
            #pragma unroll
            for (int p = 0; p < 4; p++) {
                const __half2 a = __floats2half2_rn(f[2 * p],     f[2 * p + 1]);
                const __half2 b = __floats2half2_rn(f[8 + 2 * p], f[9 + 2 * p]);
                plo[p] = *(const uint32_t*)&a;
                phi[p] = *(const uint32_t*)&b;
            }
            *(uint4*)&As[nb][amt][aks * 4 + b0][l0]     = lo;
            *(uint4*)&As[nb][amt][aks * 4 + b0 + 2][l0] = hi;
        }
        __syncthreads();
    }

    #pragma unroll
    for (int mt = 0; mt < 4; mt++) {
        const int row0 = rowBase + wm * 64 + mt * 16 + (lane >> 2);
        #pragma unroll
        for (int nt = 0; nt < 8; nt++) {
            const int col = wn * 64 + nt * 8 + (lane & 3) * 2;
            if (row0 < M)
                *(__half2*)(g_s1h + (size_t)row0 * F_HID + col) =
                    __floats2half2_rn(acc[mt][nt][0], acc[mt][nt][1]);
            if (row0 + 8 < M)
                *(__half2*)(g_s1h + (size_t)(row0 + 8) * F_HID + col) =
                    __floats2half2_rn(acc[mt][nt][2], acc[mt][nt][3]);
        }
    }
}

// ================= CSR build =================================================
__global__ void hist_dst(const int* __restrict__ dst, int E) {
    const int e = blockIdx.x * blockDim.x + threadIdx.x;
    if (e < E) atomicAdd(&g_cnt[__ldcs(dst + e)], 1);
}

__global__ void scan_block() {
    __shared__ int sh[SCAN_B];
    const int t = threadIdx.x;
    const int i = blockIdx.x * SCAN_B + t;
    const int v = (i < N_NODES) ? g_cnt[i] : 0;
    sh[t] = v;
    __syncthreads();
    #pragma unroll
    for (int o = 1; o < SCAN_B; o <<= 1) {
        int x = 0;
        if (t >= o) x = sh[t - o];
        __syncthreads();
        sh[t] += x;
        __syncthreads();
    }
    if (i < N_NODES) g_off[i] = sh[t] - v;
    if (t == SCAN_B - 1) g_blksum[blockIdx.x] = sh[t];
}

__global__ void scan_top() {
    __shared__ int sh[256];
    const int t = threadIdx.x;
    const int v = (t < SCAN_NB) ? g_blksum[t] : 0;
    sh[t] = v;
    __syncthreads();
    #pragma unroll
    for (int o = 1; o < 256; o <<= 1) {
        int x = 0;
        if (t >= o) x = sh[t - o];
        __syncthreads();
        sh[t] += x;
        __syncthreads();
    }
    if (t < SCAN_NB) g_blksum[t] = sh[t] - v;
}

// also re-zeroes g_cnt for the next graph replay and writes the sentinel
__global__ void scan_add(int E) {
    const int i = blockIdx.x * blockDim.x + threadIdx.x;
    if (i < N_NODES) {
        const int o = g_off[i] + g_blksum[i / SCAN_B];
        g_off[i] = o;
        g_pos[i] = o;
        g_cnt[i] = 0;
    }
    if (i == 0) g_off[N_NODES] = E;
}

__global__ void fill_csr(const int* __restrict__ src, const int* __restrict__ dst,
                         const float* __restrict__ ew, int E) {
    const int e = blockIdx.x * blockDim.x + threadIdx.x;
    if (e < E) {
        const int p = atomicAdd(&g_pos[__ldcs(dst + e)], 1);
        __stcs(&g_csr[p], make_int2(__ldcs(src + e), __float_as_int(__ldcs(ew + e))));
    }
}

// ======== layer-1 gather: warp per node, full 256 feats (fp16 rows) =========
__device__ __forceinline__ void accum8(float* acc, uint4 v, float w) {
    const __half2* h = (const __half2*)&v;
    #pragma unroll
    for (int j = 0; j < 4; j++) {
        const float2 f = __half22float2(h[j]);
        acc[2 * j]     = fmaf(w, f.x, acc[2 * j]);
        acc[2 * j + 1] = fmaf(w, f.y, acc[2 * j + 1]);
    }
}

__global__ __launch_bounds__(256) void gather1(const float* __restrict__ b1) {
    gdc_launch_dependents();   // let gemm2 blocks start their prologue early
    const int n = (blockIdx.x * blockDim.x + threadIdx.x) >> 5;
    const int lane = threadIdx.x & 31;

    // prologue independent of gemm1 output
    float acc[8];
    {
        const float4 blo = __ldg((const float4*)b1 + lane * 2);
        const float4 bhi = __ldg((const float4*)b1 + lane * 2 + 1);
        acc[0] = blo.x; acc[1] = blo.y; acc[2] = blo.z; acc[3] = blo.w;
        acc[4] = bhi.x; acc[5] = bhi.y; acc[6] = bhi.z; acc[7] = bhi.w;
    }
    gdc_wait();                // s1h (gemm1 output) safe to read after this

    const int beg = g_off[n];
    const int end = g_off[n + 1];

    int e = beg;
    for (; e + 7 < end; e += 8) {
        int2 c[8];
        uint4 v[8];
        #pragma unroll
        for (int i = 0; i < 8; i++) c[i] = __ldcs(&g_csr[e + i]);
        #pragma unroll
        for (int i = 0; i < 8; i++)
            v[i] = __ldg((const uint4*)(g_s1h + (size_t)c[i].x * F_HID) + lane);
        #pragma unroll
        for (int i = 0; i < 8; i++) accum8(acc, v[i], __int_as_float(c[i].y));
    }
    for (; e < end; e++) {
        const int2 c = __ldcs(&g_csr[e]);
        const uint4 v = __ldg((const uint4*)(g_s1h + (size_t)c.x * F_HID) + lane);
        accum8(acc, v, __int_as_float(c.y));
    }

    uint4 o;
    __half2* ph = (__half2*)&o;
    #pragma unroll
    for (int j = 0; j < 4; j++)
        ph[j] = __floats2half2_rn(fmaxf(acc[2 * j], 0.f), fmaxf(acc[2 * j + 1], 0.f));
    __stcs((uint4*)(g_h1h + (size_t)n * F_HID) + lane, o);
}

// ====== gemm2: support2 = a1 @ W2 (fp16 mma; W2 fragments via smem) =========
#define G2_NT 5
__global__ __launch_bounds__(256) void gemm2_mma() {
    __shared__ __align__(16) uint32_t Wf[16 * G2_NT * 32 * 2];   // 10 KB

    gdc_launch_dependents();   // let gather2 blocks start early

    const int tid = threadIdx.x;
    // prologue: stage W2 fragments (independent of gather1 output)
    for (int i = tid; i < (16 * G2_NT * 32 * 2) / 4; i += 256)
        ((uint4*)Wf)[i] = ((const uint4*)g_w2f)[i];
    __syncthreads();

    gdc_wait();                // h1h (gather1 output) safe to read after this

    const int lane = tid & 31, warp = tid >> 5;
    const int node0 = blockIdx.x * 128 + warp * 16 + (lane >> 2);
    const int node1 = node0 + 8;
    const bool v0 = node0 < N_NODES, v1 = node1 < N_NODES;

    float acc[G2_NT][4];
    #pragma unroll
    for (int nt = 0; nt < G2_NT; nt++)
        #pragma unroll
        for (int r = 0; r < 4; r++) acc[nt][r] = 0.f;

    const __half* r0 = g_h1h + (size_t)node0 * F_HID;
    const __half* r1 = g_h1h + (size_t)node1 * F_HID;

    #pragma unroll
    for (int kt = 0; kt < 16; kt++) {
        const int kof = kt * 16 + (lane & 3) * 2;
        uint32_t a[4];
        a[0] = v0 ? __ldg((const uint32_t*)(r0 + kof))     : 0u;
        a[1] = v1 ? __ldg((const uint32_t*)(r1 + kof))     : 0u;
        a[2] = v0 ? __ldg((const uint32_t*)(r0 + kof + 8)) : 0u;
        a[3] = v1 ? __ldg((const uint32_t*)(r1 + kof + 8)) : 0u;
        #pragma unroll
        for (int nt = 0; nt < G2_NT; nt++) {
            const uint32_t* bp = &Wf[(((size_t)kt * G2_NT + nt) * 32 + lane) * 2];
            const uint32_t b[2] = {bp[0], bp[1]};
            mma_f16(acc[nt], a, b);
        }
    }

    const int col = (lane & 3) * 2;
    #pragma unroll
    for (int nt = 0; nt < G2_NT; nt++) {
        if (v0)
            *(__half2*)(g_s2h + (size_t)node0 * F_OUT + nt * 8 + col) =
                __floats2half2_rn(acc[nt][0], acc[nt][1]);
        if (v1)
            *(__half2*)(g_s2h + (size_t)node1 * F_OUT + nt * 8 + col) =
                __floats2half2_rn(acc[nt][2], acc[nt][3]);
    }
}

// ========== layer-2 gather fused with log_softmax: warp per node ============
__global__ __launch_bounds__(256) void gather2_softmax(const float* __restrict__ b2,
                                                       float* __restrict__ out) {
    const int n = (blockIdx.x * blockDim.x + threadIdx.x) >> 5;
    const int lane = threadIdx.x & 31;
    const bool act = lane < (F_OUT / 2);

    // prologue independent of gemm2 output (CSR finished long before)
    float accA = 0.f, accB = 0.f;
    if (act) {
        const float2 b = __ldg((const float2*)b2 + lane);
        accA = b.x; accB = b.y;
    }
    const int beg = g_off[n];
    const int end = g_off[n + 1];

    gdc_wait();                // s2h (gemm2 output) safe to read after this

    int e = beg;
    for (; e + 1 < end; e += 2) {
        const int2 c0 = __ldcs(&g_csr[e]);
        const int2 c1 = __ldcs(&g_csr[e + 1]);
        if (act) {
            const __half2 v0 = __ldg((const __half2*)(g_s2h + (size_t)c0.x * F_OUT) + lane);
            const __half2 v1 = __ldg((const __half2*)(g_s2h + (size_t)c1.x * F_OUT) + lane);
            const float w0 = __int_as_float(c0.y);
            const float w1 = __int_as_float(c1.y);
            const float2 f0 = __half22float2(v0);
            const float2 f1 = __half22float2(v1);
            accA = fmaf(w0, f0.x, accA); accB = fmaf(w0, f0.y, accB);
            accA = fmaf(w1, f1.x, accA); accB = fmaf(w1, f1.y, accB);
        }
    }
    if (e < end) {
        const int2 c = __ldcs(&g_csr[e]);
        if (act) {
            const __half2 v = __ldg((const __half2*)(g_s2h + (size_t)c.x * F_OUT) + lane);
            const float w = __int_as_float(c.y);
            const float2 f = __half22float2(v);
            accA = fmaf(w, f.x, accA); accB = fmaf(w, f.y, accB);
        }
    }

    const float NEG_INF = __int_as_float(0xff800000);
    float m = act ? fmaxf(accA, accB) : NEG_INF;
    #pragma unroll
    for (int o = 16; o > 0; o >>= 1)
        m = fmaxf(m, __shfl_xor_sync(0xffffffffu, m, o));
    float s = act ? (expf(accA - m) + expf(accB - m)) : 0.f;
    #pragma unroll
    for (int o = 16; o > 0; o >>= 1)
        s += __shfl_xor_sync(0xffffffffu, s, o);
    const float l = m + logf(s);

    if (act)
        *((float2*)(out + (size_t)n * F_OUT) + lane) = make_float2(accA - l, accB - l);
}

// ---------------- launch ----------------------------------------------------
static void launch_pdl0(void (*k)(), dim3 grid, dim3 block) {
    cudaLaunchConfig_t cfg = {};
    cfg.gridDim = grid; cfg.blockDim = block; cfg.stream = 0;
    cudaLaunchAttribute attr[1];
    attr[0].id = cudaLaunchAttributeProgrammaticStreamSerialization;
    attr[0].val.programmaticStreamSerializationAllowed = 1;
    cfg.attrs = attr; cfg.numAttrs = 1;
    cudaLaunchKernelEx(&cfg, k);
}
static void launch_pdl1(void (*k)(const float*), dim3 grid, dim3 block, const float* a0) {
    cudaLaunchConfig_t cfg = {};
    cfg.gridDim = grid; cfg.blockDim = block; cfg.stream = 0;
    cudaLaunchAttribute attr[1];
    attr[0].id = cudaLaunchAttributeProgrammaticStreamSerialization;
    attr[0].val.programmaticStreamSerializationAllowed = 1;
    cfg.attrs = attr; cfg.numAttrs = 1;
    cudaLaunchKernelEx(&cfg, k, a0);
}
static void launch_pdl2(void (*k)(const float*, float*), dim3 grid, dim3 block,
                        const float* a0, float* a1) {
    cudaLaunchConfig_t cfg = {};
    cfg.gridDim = grid; cfg.blockDim = block; cfg.stream = 0;
    cudaLaunchAttribute attr[1];
    attr[0].id = cudaLaunchAttributeProgrammaticStreamSerialization;
    attr[0].val.programmaticStreamSerializationAllowed = 1;
    cfg.attrs = attr; cfg.numAttrs = 1;
    cudaLaunchKernelEx(&cfg, k, a0, a1);
}

extern "C" void kernel_launch(void* const* d_in, const int* in_sizes, int n_in,
                              void* d_out, int out_size) {
    const float* x   = (const float*)d_in[0];
    const int*   ei  = (const int*)d_in[1];
    const float* ew  = (const float*)d_in[2];
    const float* W1  = (const float*)d_in[3];
    const float* b1  = (const float*)d_in[4];
    const float* W2  = (const float*)d_in[5];
    const float* b2  = (const float*)d_in[6];
    float* out = (float*)d_out;

    const int E = in_sizes[2];
    const int* src = ei;
    const int* dst = ei + E;

    // Fork: CSR build + W2 pack run concurrently with W1 pack + gemm1.
    cudaStream_t s2;
    cudaStreamCreate(&s2);
    cudaEvent_t evFork, evJoin;
    cudaEventCreateWithFlags(&evFork, cudaEventDisableTiming);
    cudaEventCreateWithFlags(&evJoin, cudaEventDisableTiming);

    cudaEventRecord(evFork, 0);
    cudaStreamWaitEvent(s2, evFork, 0);

    // branch A (main stream): pack W1, then support1 = x @ W1
    pack_W1<<<128, 256>>>(W1);
    gemm1_f16<<<(N_NODES + G1_BM - 1) / G1_BM, 256>>>(x, N_NODES);

    // branch B (side stream): W2 pack + CSR build
    {
        const int nb = (N_NODES + 255) / 256;
        const int eb = (E + 255) / 256;
        pack_W2<<<10, 256, 0, s2>>>(W2);
        hist_dst<<<eb, 256, 0, s2>>>(dst, E);
        scan_block<<<SCAN_NB, SCAN_B, 0, s2>>>();
        scan_top<<<1, 256, 0, s2>>>();
        scan_add<<<nb, 256, 0, s2>>>(E);
        fill_csr<<<eb, 256, 0, s2>>>(src, dst, ew, E);
    }

    cudaEventRecord(evJoin, s2);
    cudaStreamWaitEvent(0, evJoin, 0);

    // layer-1 gather (PDL: prologue overlaps gemm1 tail)
    launch_pdl1(gather1, dim3((N_NODES * 32 + 255) / 256), dim3(256), b1);
    // support2 = a1 @ W2 (PDL: W2 smem staging overlaps gather1 straggler drain)
    launch_pdl0(gemm2_mma, dim3((N_NODES + 127) / 128), dim3(256));
    // out = log_softmax(b2 + gather(ew * support2[src])) (PDL: overlaps gemm2 drain)
    launch_pdl2(gather2_softmax, dim3((N_NODES * 32 + 255) / 256), dim3(256), b2, out);

    cudaStreamDestroy(s2);
    cudaEventDestroy(evFork);
    cudaEventDestroy(evJoin);
}

// round 14
// speedup vs baseline: 1.1201x; 1.0162x over previous
#include <cuda_runtime.h>
#include <cuda_fp16.h>
#include <cstdint>

#define N_NODES 100000
#define F_IN    512
#define F_HID   256
#define F_OUT   40
#define E_MAX   3200000

#define SCAN_B  512
#define SCAN_NB ((N_NODES + SCAN_B - 1) / SCAN_B)   // 196

// ---------------- scratch (device globals; no allocation allowed) ----------
__device__ __align__(128) __half g_s1h[(size_t)N_NODES * F_HID];   // 51.2 MB
__device__ __align__(128) __half g_h1h[(size_t)N_NODES * F_HID];   // 51.2 MB
__device__ __align__(128) __half g_s2h[(size_t)N_NODES * F_OUT];   // 8 MB

// W1 pre-packed into mma B-fragment order: [kt(32)][nt(32)][lane(32)][2]
__device__ __align__(16) uint32_t g_w1f[32 * 32 * 32 * 2];          // 256 KB
// W2 pre-packed fragments: [kt(16)][nt(5)][lane(32)][2]
__device__ __align__(16) uint32_t g_w2f[16 * 5 * 32 * 2];           // 10 KB

__device__ int  g_cnt[N_NODES];          // zero at module load; re-zeroed by scan_add
__device__ int  g_off[N_NODES + 1];      // +1 sentinel = E
__device__ int  g_pos[N_NODES];
__device__ int  g_blksum[SCAN_NB];
__device__ __align__(16) int2 g_csr[E_MAX];    // (src, float-bits of w)

// ---------------- PDL helpers (no-ops when attr not set) --------------------
__device__ __forceinline__ void gdc_wait() {
    asm volatile("griddepcontrol.wait;" ::: "memory");
}
__device__ __forceinline__ void gdc_launch_dependents() {
    asm volatile("griddepcontrol.launch_dependents;");
}

// ---------------- fp16 mma helper -------------------------------------------
__device__ __forceinline__ void mma_f16(float* c, const uint32_t* a, const uint32_t* b) {
    asm volatile("mma.sync.aligned.m16n8k16.row.col.f32.f16.f16.f32 "
                 "{%0,%1,%2,%3}, {%4,%5,%6,%7}, {%8,%9}, {%0,%1,%2,%3};"
                 : "+f"(c[0]), "+f"(c[1]), "+f"(c[2]), "+f"(c[3])
                 : "r"(a[0]), "r"(a[1]), "r"(a[2]), "r"(a[3]),
                   "r"(b[0]), "r"(b[1]));
}

// ================ pack W1 (fp32 [512,256]) into fragment order ===============
__global__ void pack_W1(const float* __restrict__ W1) {
    gdc_launch_dependents();   // gemm1 may start its A-prologue immediately
    const int idx = blockIdx.x * blockDim.x + threadIdx.x;   // 0..32767
    if (idx >= 32 * 32 * 32) return;
    const int kt = idx >> 10;
    const int rem = idx & 1023;
    const int nt = rem >> 5;
    const int ln = rem & 31;
    const int n = nt * 8 + (ln >> 2);
    const int k = kt * 16 + (ln & 3) * 2;
    const __half2 h0 = __floats2half2_rn(W1[(size_t)k * F_HID + n],
                                         W1[(size_t)(k + 1) * F_HID + n]);
    const __half2 h1 = __floats2half2_rn(W1[(size_t)(k + 8) * F_HID + n],
                                         W1[(size_t)(k + 9) * F_HID + n]);
    g_w1f[idx * 2]     = *(const uint32_t*)&h0;
    g_w1f[idx * 2 + 1] = *(const uint32_t*)&h1;
}

// ================ pack W2 (fp32 [256,40]) into fragment order ================
__global__ void pack_W2(const float* __restrict__ W2) {
    const int idx = blockIdx.x * blockDim.x + threadIdx.x;   // 0..2559
    if (idx >= 16 * 5 * 32) return;
    const int kt = idx / (5 * 32);
    const int rem = idx % (5 * 32);
    const int nt = rem / 32;
    const int ln = rem % 32;
    const int n = nt * 8 + (ln >> 2);
    const int k0 = kt * 16 + (ln & 3) * 2;
    const __half2 h0 = __floats2half2_rn(W2[(size_t)k0 * F_OUT + n],
                                         W2[(size_t)(k0 + 1) * F_OUT + n]);
    const __half2 h1 = __floats2half2_rn(W2[(size_t)(k0 + 8) * F_OUT + n],
                                         W2[(size_t)(k0 + 9) * F_OUT + n]);
    g_w2f[idx * 2]     = *(const uint32_t*)&h0;
    g_w2f[idx * 2 + 1] = *(const uint32_t*)&h1;
}

// ================= gemm1: support1 = x @ W1  (fp16 MMA, fp16 out) ==========
#define G1_BM 128
#define G1_BK 32
#define AS_PAD 36

__global__ __launch_bounds__(256, 1) void gemm1_f16(const float* __restrict__ A, int M) {
    __shared__ __align__(16) uint32_t As[2][8][8][AS_PAD];   // 18.4 KB

    const int tid  = threadIdx.x;
    const int lane = tid & 31;
    const int warp = tid >> 5;
    const int wm = warp & 1;
    const int wn = warp >> 1;
    const int rowBase = blockIdx.x * G1_BM;

    const int ar  = tid >> 1;
    const int aks = tid & 1;
    const int amt = ar >> 4, arr = ar & 15;
    const int b0  = arr >> 3;
    const int l0  = (arr & 7) * 4;

    float acc[4][8][4];
    #pragma unroll
    for (int mt = 0; mt < 4; mt++)
        #pragma unroll
        for (int nt = 0; nt < 8; nt++)
            #pragma unroll
            for (int r = 0; r < 4; r++) acc[mt][nt][r] = 0.f;

    const int arow = rowBase + ar;
    const float* Arow = A + (size_t)arow * F_IN + aks * 16;
    float4 pa[4];

    // prologue: A tile 0 (independent of pack_W1 output)
    {
        #pragma unroll
        for (int j = 0; j < 4; j++)
            pa[j] = (arow < M) ? __ldcs((const float4*)(Arow + 4 * j))
                               : make_float4(0.f, 0.f, 0.f, 0.f);
        const float* f = (const float*)pa;
        uint4 lo, hi;
        uint32_t* plo = (uint32_t*)&lo;
        uint32_t* phi = (uint32_t*)&hi;
        #pragma unroll
        for (int p = 0; p < 4; p++) {
            const __half2 a = __floats2half2_rn(f[2 * p],     f[2 * p + 1]);
            const __half2 b = __floats2half2_rn(f[8 + 2 * p], f[9 + 2 * p]);
            plo[p] = *(const uint32_t*)&a;
            phi[p] = *(const uint32_t*)&b;
        }
        *(uint4*)&As[0][amt][aks * 4 + b0][l0]     = lo;
        *(uint4*)&As[0][amt][aks * 4 + b0 + 2][l0] = hi;
    }
    __syncthreads();

    gdc_wait();   // g_w1f (pack_W1 output) safe to read after this

    const int NT = F_IN / G1_BK;   // 16
    for (int t = 0; t < NT; t++) {
        const int buf = t & 1;
        if (t + 1 < NT) {
            const float* Anext = Arow + (t + 1) * G1_BK;
            #pragma unroll
            for (int j = 0; j < 4; j++)
                pa[j] = (arow < M) ? __ldcs((const float4*)(Anext + 4 * j))
                                   : make_float4(0.f, 0.f, 0.f, 0.f);
        }

        #pragma unroll
        for (int ks = 0; ks < 2; ks++) {
            const int kt = t * 2 + ks;
            uint32_t bfr[8][2];
            #pragma unroll
            for (int nt = 0; nt < 8; nt++) {
                const uint2 v = __ldg((const uint2*)
                    &g_w1f[(((size_t)kt * 32 + wn * 8 + nt) * 32 + lane) * 2]);
                bfr[nt][0] = v.x; bfr[nt][1] = v.y;
            }
            uint32_t afr[4][4];
            #pragma unroll
            for (int mt = 0; mt < 4; mt++)
                #pragma unroll
                for (int r = 0; r < 4; r++)
                    afr[mt][r] = As[buf][wm * 4 + mt][ks * 4 + r][lane];
            #pragma unroll
            for (int mt = 0; mt < 4; mt++)
                #pragma unroll
                for (int nt = 0; nt < 8; nt++)
                    mma_f16(acc[mt][nt], afr[mt], bfr[nt]);
        }

        if (t + 1 < NT) {
            const int nb = buf ^ 1;
            const float* f = (const float*)pa;
            uint4 lo, hi;
            uint32_t* plo = (uint32_t*)&lo;
            uint32_t* phi = (uint32_t*)&hi;
            #pragma unroll
            for (int p = 0; p < 4; p++) {
                const __half2 a = __floats2half2_rn(f[2 * p],     f[2 * p + 1]);
                const __half2 b = __floats2half2_rn(f[8 + 2 * p], f[9 + 2 * p]);
                plo[p] = *(const uint32_t*)&a;
                phi[p] = *(const uint32_t*)&b;
            }
            *(uint4*)&As[nb][amt][aks * 4 + b0][l0]     = lo;
            *(uint4*)&As[nb][amt][aks * 4 + b0 + 2][l0] = hi;
        }
        __syncthreads();
    }

    gdc_launch_dependents();   // let gather1 ramp during the epilogue/drain

    #pragma unroll
    for (int mt = 0; mt < 4; mt++) {
        const int row0 = rowBase + wm * 64 + mt * 16 + (lane >> 2);
        #pragma unroll
        for (int nt = 0; nt < 8; nt++) {
            const int col = wn * 64 + nt * 8 + (lane & 3) * 2;
            if (row0 < M)
                *(__half2*)(g_s1h + (size_t)row0 * F_HID + col) =
                    __floats2half2_rn(acc[mt][nt][0], acc[mt][nt][1]);
            if (row0 + 8 < M)
                *(__half2*)(g_s1h + (size_t)(row0 + 8) * F_HID + col) =
                    __floats2half2_rn(acc[mt][nt][2], acc[mt][nt][3]);
        }
    }
}

// ================= CSR build =================================================
__global__ void hist_dst(const int* __restrict__ dst, int E) {
    const int e = blockIdx.x * blockDim.x + threadIdx.x;
    if (e < E) atomicAdd(&g_cnt[__ldcs(dst + e)], 1);
}

__global__ void scan_block() {
    __shared__ int sh[SCAN_B];
    const int t = threadIdx.x;
    const int i = blockIdx.x * SCAN_B + t;
    const int v = (i < N_NODES) ? g_cnt[i] : 0;
    sh[t] = v;
    __syncthreads();
    #pragma unroll
    for (int o = 1; o < SCAN_B; o <<= 1) {
        int x = 0;
        if (t >= o) x = sh[t - o];
        __syncthreads();
        sh[t] += x;
        __syncthreads();
    }
    if (i < N_NODES) g_off[i] = sh[t] - v;
    if (t == SCAN_B - 1) g_blksum[blockIdx.x] = sh[t];
}

__global__ void scan_top() {
    __shared__ int sh[256];
    const int t = threadIdx.x;
    const int v = (t < SCAN_NB) ? g_blksum[t] : 0;
    sh[t] = v;
    __syncthreads();
    #pragma unroll
    for (int o = 1; o < 256; o <<= 1) {
        int x = 0;
        if (t >= o) x = sh[t - o];
        __syncthreads();
        sh[t] += x;
        __syncthreads();
    }
    if (t < SCAN_NB) g_blksum[t] = sh[t] - v;
}

// also re-zeroes g_cnt for the next graph replay and writes the sentinel
__global__ void scan_add(int E) {
    const int i = blockIdx.x * blockDim.x + threadIdx.x;
    if (i < N_NODES) {
        const int o = g_off[i] + g_blksum[i / SCAN_B];
        g_off[i] = o;
        g_pos[i] = o;
        g_cnt[i] = 0;
    }
    if (i == 0) g_off[N_NODES] = E;
}

__global__ void fill_csr(const int* __restrict__ src, const int* __restrict__ dst,
                         const float* __restrict__ ew, int E) {
    const int e = blockIdx.x * blockDim.x + threadIdx.x;
    if (e < E) {
        const int p = atomicAdd(&g_pos[__ldcs(dst + e)], 1);
        __stcs(&g_csr[p], make_int2(__ldcs(src + e), __float_as_int(__ldcs(ew + e))));
    }
}

// ======== layer-1 gather: warp per node, full 256 feats (fp16 rows) =========
__device__ __forceinline__ void accum8(float* acc, uint4 v, float w) {
    const __half2* h = (const __half2*)&v;
    #pragma unroll
    for (int j = 0; j < 4; j++) {
        const float2 f = __half22float2(h[j]);
        acc[2 * j]     = fmaf(w, f.x, acc[2 * j]);
        acc[2 * j + 1] = fmaf(w, f.y, acc[2 * j + 1]);
    }
}

__global__ __launch_bounds__(256) void gather1(const float* __restrict__ b1) {
    gdc_launch_dependents();   // let gemm2 blocks stage W2 early
    const int n = (blockIdx.x * blockDim.x + threadIdx.x) >> 5;
    const int lane = threadIdx.x & 31;

    // prologue independent of gemm1 output
    float acc[8];
    {
        const float4 blo = __ldg((const float4*)b1 + lane * 2);
        const float4 bhi = __ldg((const float4*)b1 + lane * 2 + 1);
        acc[0] = blo.x; acc[1] = blo.y; acc[2] = blo.z; acc[3] = blo.w;
        acc[4] = bhi.x; acc[5] = bhi.y; acc[6] = bhi.z; acc[7] = bhi.w;
    }
    gdc_wait();                // s1h (gemm1 output) safe to read after this

    const int beg = g_off[n];
    const int end = g_off[n + 1];

    int e = beg;
    for (; e + 7 < end; e += 8) {
        int2 c[8];
        uint4 v[8];
        #pragma unroll
        for (int i = 0; i < 8; i++) c[i] = __ldcs(&g_csr[e + i]);
        #pragma unroll
        for (int i = 0; i < 8; i++)
            v[i] = __ldg((const uint4*)(g_s1h + (size_t)c[i].x * F_HID) + lane);
        #pragma unroll
        for (int i = 0; i < 8; i++) accum8(acc, v[i], __int_as_float(c[i].y));
    }
    for (; e < end; e++) {
        const int2 c = __ldcs(&g_csr[e]);
        const uint4 v = __ldg((const uint4*)(g_s1h + (size_t)c.x * F_HID) + lane);
        accum8(acc, v, __int_as_float(c.y));
    }

    uint4 o;
    __half2* ph = (__half2*)&o;
    #pragma unroll
    for (int j = 0; j < 4; j++)
        ph[j] = __floats2half2_rn(fmaxf(acc[2 * j], 0.f), fmaxf(acc[2 * j + 1], 0.f));
    __stcs((uint4*)(g_h1h + (size_t)n * F_HID) + lane, o);
}

// ====== gemm2: support2 = a1 @ W2 (fp16 mma; W2 fragments via smem) =========
#define G2_NT 5
__global__ __launch_bounds__(256) void gemm2_mma() {
    __shared__ __align__(16) uint32_t Wf[16 * G2_NT * 32 * 2];   // 10 KB

    gdc_launch_dependents();   // let gather2 blocks start early

    const int tid = threadIdx.x;
    // prologue: stage W2 fragments (independent of gather1 output)
    for (int i = tid; i < (16 * G2_NT * 32 * 2) / 4; i += 256)
        ((uint4*)Wf)[i] = ((const uint4*)g_w2f)[i];
    __syncthreads();

    gdc_wait();                // h1h (gather1 output) safe to read after this

    const int lane = tid & 31, warp = tid >> 5;
    const int node0 = blockIdx.x * 128 + warp * 16 + (lane >> 2);
    const int node1 = node0 + 8;
    const bool v0 = node0 < N_NODES, v1 = node1 < N_NODES;

    float acc[G2_NT][4];
    #pragma unroll
    for (int nt = 0; nt < G2_NT; nt++)
        #pragma unroll
        for (int r = 0; r < 4; r++) acc[nt][r] = 0.f;

    const __half* r0 = g_h1h + (size_t)node0 * F_HID;
    const __half* r1 = g_h1h + (size_t)node1 * F_HID;

    #pragma unroll
    for (int kt = 0; kt < 16; kt++) {
        const int kof = kt * 16 + (lane & 3) * 2;
        uint32_t a[4];
        a[0] = v0 ? __ldg((const uint32_t*)(r0 + kof))     : 0u;
        a[1] = v1 ? __ldg((const uint32_t*)(r1 + kof))     : 0u;
        a[2] = v0 ? __ldg((const uint32_t*)(r0 + kof + 8)) : 0u;
        a[3] = v1 ? __ldg((const uint32_t*)(r1 + kof + 8)) : 0u;
        #pragma unroll
        for (int nt = 0; nt < G2_NT; nt++) {
            const uint32_t* bp = &Wf[(((size_t)kt * G2_NT + nt) * 32 + lane) * 2];
            const uint32_t b[2] = {bp[0], bp[1]};
            mma_f16(acc[nt], a, b);
        }
    }

    const int col = (lane & 3) * 2;
    #pragma unroll
    for (int nt = 0; nt < G2_NT; nt++) {
        if (v0)
            *(__half2*)(g_s2h + (size_t)node0 * F_OUT + nt * 8 + col) =
                __floats2half2_rn(acc[nt][0], acc[nt][1]);
        if (v1)
            *(__half2*)(g_s2h + (size_t)node1 * F_OUT + nt * 8 + col) =
                __floats2half2_rn(acc[nt][2], acc[nt][3]);
    }
}

// ========== layer-2 gather + log_softmax: warp/node, 3 edge-slots ==========
// Lanes 0..29 = 3 slots x 10 lanes; lane loads uint2 (4 feats) per edge.
// Slot partials combined via shuffles; lanes 0..9 do softmax + float4 store.
__global__ __launch_bounds__(256) void gather2_softmax(const float* __restrict__ b2,
                                                       float* __restrict__ out) {
    const int n = (blockIdx.x * blockDim.x + threadIdx.x) >> 5;
    const int lane = threadIdx.x & 31;
    const int slot = lane / 10;          // 0,1,2 (3 for lanes 30,31)
    const int pos  = lane - slot * 10;   // 0..9
    const bool act = lane < 30;

    const int beg = g_off[n];
    const int end = g_off[n + 1];

    float acc[4] = {0.f, 0.f, 0.f, 0.f};

    gdc_wait();                // s2h (gemm2 output) safe to read after this

    const int total = end - beg;
    int base = 0;
    for (; base + 6 <= total; base += 6) {
        const int e0 = beg + base + slot;
        const int e1 = e0 + 3;
        int2 c0, c1;
        uint2 v0, v1;
        if (act) {
            c0 = __ldcs(&g_csr[e0]);
            c1 = __ldcs(&g_csr[e1]);
            v0 = __ldg((const uint2*)(g_s2h + (size_t)c0.x * F_OUT) + pos);
            v1 = __ldg((const uint2*)(g_s2h + (size_t)c1.x * F_OUT) + pos);
            const float w0 = __int_as_float(c0.y);
            const float w1 = __int_as_float(c1.y);
            const __half2* h0 = (const __half2*)&v0;
            const __half2* h1 = (const __half2*)&v1;
            const float2 a0 = __half22float2(h0[0]), a1 = __half22float2(h0[1]);
            const float2 b0 = __half22float2(h1[0]), b1 = __half22float2(h1[1]);
            acc[0] = fmaf(w0, a0.x, acc[0]); acc[1] = fmaf(w0, a0.y, acc[1]);
            acc[2] = fmaf(w0, a1.x, acc[2]); acc[3] = fmaf(w0, a1.y, acc[3]);
            acc[0] = fmaf(w1, b0.x, acc[0]); acc[1] = fmaf(w1, b0.y, acc[1]);
            acc[2] = fmaf(w1, b1.x, acc[2]); acc[3] = fmaf(w1, b1.y, acc[3]);
        }
    }
    for (; base < total; base += 3) {
        const int e = beg + base + slot;
        if (act && e < end) {
            const int2 c = __ldcs(&g_csr[e]);
            const uint2 v = __ldg((const uint2*)(g_s2h + (size_t)c.x * F_OUT) + pos);
            const float w = __int_as_float(c.y);
            const __half2* h = (const __half2*)&v;
            const float2 f0 = __half22float2(h[0]), f1 = __half22float2(h[1]);
            acc[0] = fmaf(w, f0.x, acc[0]); acc[1] = fmaf(w, f0.y, acc[1]);
            acc[2] = fmaf(w, f1.x, acc[2]); acc[3] = fmaf(w, f1.y, acc[3]);
        }
    }

    // combine the 3 slots: feature group p lives at lanes p, p+10, p+20
    #pragma unroll
    for (int j = 0; j < 4; j++) {
        const float a10 = __shfl_sync(0xffffffffu, acc[j], pos + 10);
        const float a20 = __shfl_sync(0xffffffffu, acc[j], pos + 20);
        acc[j] += a10 + a20;
    }

    const bool own = lane < 10;
    if (own) {
        const float4 b = __ldg((const float4*)b2 + lane);
        acc[0] += b.x; acc[1] += b.y; acc[2] += b.z; acc[3] += b.w;
    }

    const float NEG_INF = __int_as_float(0xff800000);
    float m = own ? fmaxf(fmaxf(acc[0], acc[1]), fmaxf(acc[2], acc[3])) : NEG_INF;
    #pragma unroll
    for (int o = 16; o > 0; o >>= 1)
        m = fmaxf(m, __shfl_xor_sync(0xffffffffu, m, o));
    float s = own ? (expf(acc[0] - m) + expf(acc[1] - m) +
                     expf(acc[2] - m) + expf(acc[3] - m)) : 0.f;
    #pragma unroll
    for (int o = 16; o > 0; o >>= 1)
        s += __shfl_xor_sync(0xffffffffu, s, o);
    const float l = m + logf(s);

    if (own) {
        const float4 o4 = make_float4(acc[0] - l, acc[1] - l, acc[2] - l, acc[3] - l);
        *((float4*)(out + (size_t)n * F_OUT) + lane) = o4;
    }
}

// ---------------- launch ----------------------------------------------------
template <typename... Args>
static void launch_pdl(void (*k)(Args...), dim3 grid, dim3 block, Args... args) {
    cudaLaunchConfig_t cfg = {};
    cfg.gridDim = grid; cfg.blockDim = block; cfg.stream = 0;
    cudaLaunchAttribute attr[1];
    attr[0].id = cudaLaunchAttributeProgrammaticStreamSerialization;
    attr[0].val.programmaticStreamSerializationAllowed = 1;
    cfg.attrs = attr; cfg.numAttrs = 1;
    cudaLaunchKernelEx(&cfg, k, args...);
}

extern "C" void kernel_launch(void* const* d_in, const int* in_sizes, int n_in,
                              void* d_out, int out_size) {
    const float* x   = (const float*)d_in[0];
    const int*   ei  = (const int*)d_in[1];
    const float* ew  = (const float*)d_in[2];
    const float* W1  = (const float*)d_in[3];
    const float* b1  = (const float*)d_in[4];
    const float* W2  = (const float*)d_in[5];
    const float* b2  = (const float*)d_in[6];
    float* out = (float*)d_out;

    const int E = in_sizes[2];
    const int* src = ei;
    const int* dst = ei + E;

    // Fork: CSR build + W2 pack run concurrently with W1 pack + gemm1.
    cudaStream_t s2;
    cudaStreamCreate(&s2);
    cudaEvent_t evFork, evJoin;
    cudaEventCreateWithFlags(&evFork, cudaEventDisableTiming);
    cudaEventCreateWithFlags(&evJoin, cudaEventDisableTiming);

    cudaEventRecord(evFork, 0);
    cudaStreamWaitEvent(s2, evFork, 0);

    // branch A (main stream): pack W1, then support1 = x @ W1 (PDL-chained)
    pack_W1<<<128, 256>>>(W1);
    launch_pdl(gemm1_f16, dim3((N_NODES + G1_BM - 1) / G1_BM), dim3(256),
               x, (int)N_NODES);

    // branch B (side stream): W2 pack + CSR build
    {
        const int nb = (N_NODES + 255) / 256;
        const int eb = (E + 255) / 256;
        pack_W2<<<10, 256, 0, s2>>>(W2);
        hist_dst<<<eb, 256, 0, s2>>>(dst, E);
        scan_block<<<SCAN_NB, SCAN_B, 0, s2>>>();
        scan_top<<<1, 256, 0, s2>>>();
        scan_add<<<nb, 256, 0, s2>>>(E);
        fill_csr<<<eb, 256, 0, s2>>>(src, dst, ew, E);
    }

    cudaEventRecord(evJoin, s2);
    cudaStreamWaitEvent(0, evJoin, 0);

    // layer-1 gather (PDL: prologue + ramp overlap gemm1 epilogue/drain)
    launch_pdl(gather1, dim3((N_NODES * 32 + 255) / 256), dim3(256), b1);
    // support2 = a1 @ W2 (PDL: W2 smem staging overlaps gather1 straggler drain)
    launch_pdl(gemm2_mma, dim3((N_NODES + 127) / 128), dim3(256));
    // out = log_softmax(b2 + gather(ew * support2[src])) (PDL: overlaps gemm2 drain)
    launch_pdl(gather2_softmax, dim3((N_NODES * 32 + 255) / 256), dim3(256), b2, out);

    cudaStreamDestroy(s2);
    cudaEventDestroy(evFork);
    cudaEventDestroy(evJoin);
}

// round 15
// speedup vs baseline: 1.1503x; 1.0270x over previous
#include <cuda_runtime.h>
#include <cuda_fp16.h>
#include <cstdint>

#define N_NODES 100000
#define F_IN    512
#define F_HID   256
#define F_OUT   40
#define E_MAX   3200000

#define SCAN_B  512
#define SCAN_NB ((N_NODES + SCAN_B - 1) / SCAN_B)   // 196

// ---------------- scratch (device globals; no allocation allowed) ----------
__device__ __align__(128) __half g_s1h[(size_t)N_NODES * F_HID];   // 51.2 MB
__device__ __align__(128) __half g_h1h[(size_t)N_NODES * F_HID];   // 51.2 MB
__device__ __align__(128) __half g_s2h[(size_t)N_NODES * F_OUT];   // 8 MB

// W1 pre-packed into mma B-fragment order: [kt(32)][nt(32)][lane(32)][2]
__device__ __align__(16) uint32_t g_w1f[32 * 32 * 32 * 2];          // 256 KB
// W2 pre-packed fragments: [kt(16)][nt(5)][lane(32)][2]
__device__ __align__(16) uint32_t g_w2f[16 * 5 * 32 * 2];           // 10 KB

__device__ int  g_cnt[N_NODES];          // zero at module load; re-zeroed by scan_add
__device__ int  g_off[N_NODES + 1];      // +1 sentinel = E
__device__ int  g_pos[N_NODES];
__device__ int  g_blksum[SCAN_NB];
__device__ __align__(16) int2 g_csr[E_MAX];    // (src, float-bits of w)

// ---------------- PDL helpers (no-ops when attr not set) --------------------
__device__ __forceinline__ void gdc_wait() {
    asm volatile("griddepcontrol.wait;" ::: "memory");
}
__device__ __forceinline__ void gdc_launch_dependents() {
    asm volatile("griddepcontrol.launch_dependents;");
}

// ---------------- fp16 mma helper -------------------------------------------
__device__ __forceinline__ void mma_f16(float* c, const uint32_t* a, const uint32_t* b) {
    asm volatile("mma.sync.aligned.m16n8k16.row.col.f32.f16.f16.f32 "
                 "{%0,%1,%2,%3}, {%4,%5,%6,%7}, {%8,%9}, {%0,%1,%2,%3};"
                 : "+f"(c[0]), "+f"(c[1]), "+f"(c[2]), "+f"(c[3])
                 : "r"(a[0]), "r"(a[1]), "r"(a[2]), "r"(a[3]),
                   "r"(b[0]), "r"(b[1]));
}

// ================ pack W1 (fp32 [512,256]) into fragment order ===============
__global__ void pack_W1(const float* __restrict__ W1) {
    gdc_launch_dependents();   // gemm1 may start its A-prologue immediately
    const int idx = blockIdx.x * blockDim.x + threadIdx.x;   // 0..32767
    if (idx >= 32 * 32 * 32) return;
    const int kt = idx >> 10;
    const int rem = idx & 1023;
    const int nt = rem >> 5;
    const int ln = rem & 31;
    const int n = nt * 8 + (ln >> 2);
    const int k = kt * 16 + (ln & 3) * 2;
    const __half2 h0 = __floats2half2_rn(W1[(size_t)k * F_HID + n],
                                         W1[(size_t)(k + 1) * F_HID + n]);
    const __half2 h1 = __floats2half2_rn(W1[(size_t)(k + 8) * F_HID + n],
                                         W1[(size_t)(k + 9) * F_HID + n]);
    g_w1f[idx * 2]     = *(const uint32_t*)&h0;
    g_w1f[idx * 2 + 1] = *(const uint32_t*)&h1;
}

// ================ pack W2 (fp32 [256,40]) into fragment order ================
__global__ void pack_W2(const float* __restrict__ W2) {
    const int idx = blockIdx.x * blockDim.x + threadIdx.x;   // 0..2559
    if (idx >= 16 * 5 * 32) return;
    const int kt = idx / (5 * 32);
    const int rem = idx % (5 * 32);
    const int nt = rem / 32;
    const int ln = rem % 32;
    const int n = nt * 8 + (ln >> 2);
    const int k0 = kt * 16 + (ln & 3) * 2;
    const __half2 h0 = __floats2half2_rn(W2[(size_t)k0 * F_OUT + n],
                                         W2[(size_t)(k0 + 1) * F_OUT + n]);
    const __half2 h1 = __floats2half2_rn(W2[(size_t)(k0 + 8) * F_OUT + n],
                                         W2[(size_t)(k0 + 9) * F_OUT + n]);
    g_w2f[idx * 2]     = *(const uint32_t*)&h0;
    g_w2f[idx * 2 + 1] = *(const uint32_t*)&h1;
}

// ================= gemm1: support1 = x @ W1  (fp16 MMA, fp16 out) ==========
// Block tile 128(M) x 128(N) x 32(K); 8 warps, warp tile 64x32.
// 2 CTAs/SM (64-reg accumulators) for latency hiding; sibling col-blocks
// share A rows via L2.
#define G1_BM 128
#define G1_BK 32
#define AS_PAD 36

__global__ __launch_bounds__(256, 2) void gemm1_f16(const float* __restrict__ A, int M) {
    __shared__ __align__(16) uint32_t As[2][8][8][AS_PAD];   // 18.4 KB

    const int tid  = threadIdx.x;
    const int lane = tid & 31;
    const int warp = tid >> 5;
    const int wm = warp & 1;      // 0..1 -> 64-row slab
    const int wn = warp >> 1;     // 0..3 -> 32-col slab
    const int rowBase = blockIdx.y * G1_BM;
    const int ntBase  = blockIdx.x * 16;   // 16 n-tiles (128 cols) per block

    const int ar  = tid >> 1;
    const int aks = tid & 1;
    const int amt = ar >> 4, arr = ar & 15;
    const int b0  = arr >> 3;
    const int l0  = (arr & 7) * 4;

    float acc[4][4][4];
    #pragma unroll
    for (int mt = 0; mt < 4; mt++)
        #pragma unroll
        for (int nt = 0; nt < 4; nt++)
            #pragma unroll
            for (int r = 0; r < 4; r++) acc[mt][nt][r] = 0.f;

    const int arow = rowBase + ar;
    const float* Arow = A + (size_t)arow * F_IN + aks * 16;
    float4 pa[4];

    // prologue: A tile 0 (independent of pack_W1 output)
    {
        #pragma unroll
        for (int j = 0; j < 4; j++)
            pa[j] = (arow < M) ? __ldcs((const float4*)(Arow + 4 * j))
                               : make_float4(0.f, 0.f, 0.f, 0.f);
        const float* f = (const float*)pa;
        uint4 lo, hi;
        uint32_t* plo = (uint32_t*)&lo;
        uint32_t* phi = (uint32_t*)&hi;
        #pragma unroll
        for (int p = 0; p < 4; p++) {
            const __half2 a = __floats2half2_rn(f[2 * p],     f[2 * p + 1]);
            const __half2 b = __floats2half2_rn(f[8 + 2 * p], f[9 + 2 * p]);
            plo[p] = *(const uint32_t*)&a;
            phi[p] = *(const uint32_t*)&b;
        }
        *(uint4*)&As[0][amt][aks * 4 + b0][l0]     = lo;
        *(uint4*)&As[0][amt][aks * 4 + b0 + 2][l0] = hi;
    }
    __syncthreads();

    gdc_wait();   // g_w1f (pack_W1 output) safe to read after this

    const int NT = F_IN / G1_BK;   // 16
    for (int t = 0; t < NT; t++) {
        const int buf = t & 1;
        if (t + 1 < NT) {
            const float* Anext = Arow + (t + 1) * G1_BK;
            #pragma unroll
            for (int j = 0; j < 4; j++)
                pa[j] = (arow < M) ? __ldcs((const float4*)(Anext + 4 * j))
                                   : make_float4(0.f, 0.f, 0.f, 0.f);
        }

        #pragma unroll
        for (int ks = 0; ks < 2; ks++) {
            const int kt = t * 2 + ks;
            uint32_t bfr[4][2];
            #pragma unroll
            for (int nt = 0; nt < 4; nt++) {
                const uint2 v = __ldg((const uint2*)
                    &g_w1f[(((size_t)kt * 32 + ntBase + wn * 4 + nt) * 32 + lane) * 2]);
                bfr[nt][0] = v.x; bfr[nt][1] = v.y;
            }
            uint32_t afr[4][4];
            #pragma unroll
            for (int mt = 0; mt < 4; mt++)
                #pragma unroll
                for (int r = 0; r < 4; r++)
                    afr[mt][r] = As[buf][wm * 4 + mt][ks * 4 + r][lane];
            #pragma unroll
            for (int mt = 0; mt < 4; mt++)
                #pragma unroll
                for (int nt = 0; nt < 4; nt++)
                    mma_f16(acc[mt][nt], afr[mt], bfr[nt]);
        }

        if (t + 1 < NT) {
            const int nb = buf ^ 1;
            const float* f = (const float*)pa;
            uint4 lo, hi;
            uint32_t* plo = (uint32_t*)&lo;
            uint32_t* phi = (uint32_t*)&hi;
            #pragma unroll
            for (int p = 0; p < 4; p++) {
                const __half2 a = __floats2half2_rn(f[2 * p],     f[2 * p + 1]);
                const __half2 b = __floats2half2_rn(f[8 + 2 * p], f[9 + 2 * p]);
                plo[p] = *(const uint32_t*)&a;
                phi[p] = *(const uint32_t*)&b;
            }
            *(uint4*)&As[nb][amt][aks * 4 + b0][l0]     = lo;
            *(uint4*)&As[nb][amt][aks * 4 + b0 + 2][l0] = hi;
        }
        __syncthreads();
    }

    gdc_launch_dependents();   // let gather1 ramp during the epilogue/drain

    #pragma unroll
    for (int mt = 0; mt < 4; mt++) {
        const int row0 = rowBase + wm * 64 + mt * 16 + (lane >> 2);
        #pragma unroll
        for (int nt = 0; nt < 4; nt++) {
            const int col = (ntBase + wn * 4 + nt) * 8 + (lane & 3) * 2;
            if (row0 < M)
                *(__half2*)(g_s1h + (size_t)row0 * F_HID + col) =
                    __floats2half2_rn(acc[mt][nt][0], acc[mt][nt][1]);
            if (row0 + 8 < M)
                *(__half2*)(g_s1h + (size_t)(row0 + 8) * F_HID + col) =
                    __floats2half2_rn(acc[mt][nt][2], acc[mt][nt][3]);
        }
    }
}

// ================= CSR build =================================================
__global__ void hist_dst(const int* __restrict__ dst, int E) {
    const int e = blockIdx.x * blockDim.x + threadIdx.x;
    if (e < E) atomicAdd(&g_cnt[__ldcs(dst + e)], 1);
}

__global__ void scan_block() {
    __shared__ int sh[SCAN_B];
    const int t = threadIdx.x;
    const int i = blockIdx.x * SCAN_B + t;
    const int v = (i < N_NODES) ? g_cnt[i] : 0;
    sh[t] = v;
    __syncthreads();
    #pragma unroll
    for (int o = 1; o < SCAN_B; o <<= 1) {
        int x = 0;
        if (t >= o) x = sh[t - o];
        __syncthreads();
        sh[t] += x;
        __syncthreads();
    }
    if (i < N_NODES) g_off[i] = sh[t] - v;
    if (t == SCAN_B - 1) g_blksum[blockIdx.x] = sh[t];
}

__global__ void scan_top() {
    __shared__ int sh[256];
    const int t = threadIdx.x;
    const int v = (t < SCAN_NB) ? g_blksum[t] : 0;
    sh[t] = v;
    __syncthreads();
    #pragma unroll
    for (int o = 1; o < 256; o <<= 1) {
        int x = 0;
        if (t >= o) x = sh[t - o];
        __syncthreads();
        sh[t] += x;
        __syncthreads();
    }
    if (t < SCAN_NB) g_blksum[t] = sh[t] - v;
}

// also re-zeroes g_cnt for the next graph replay and writes the sentinel
__global__ void scan_add(int E) {
    const int i = blockIdx.x * blockDim.x + threadIdx.x;
    if (i < N_NODES) {
        const int o = g_off[i] + g_blksum[i / SCAN_B];
        g_off[i] = o;
        g_pos[i] = o;
        g_cnt[i] = 0;
    }
    if (i == 0) g_off[N_NODES] = E;
}

__global__ void fill_csr(const int* __restrict__ src, const int* __restrict__ dst,
                         const float* __restrict__ ew, int E) {
    const int e = blockIdx.x * blockDim.x + threadIdx.x;
    if (e < E) {
        const int p = atomicAdd(&g_pos[__ldcs(dst + e)], 1);
        __stcs(&g_csr[p], make_int2(__ldcs(src + e), __float_as_int(__ldcs(ew + e))));
    }
}

// ======== layer-1 gather: warp per node, full 256 feats (fp16 rows) =========
__device__ __forceinline__ void accum8(float* acc, uint4 v, float w) {
    const __half2* h = (const __half2*)&v;
    #pragma unroll
    for (int j = 0; j < 4; j++) {
        const float2 f = __half22float2(h[j]);
        acc[2 * j]     = fmaf(w, f.x, acc[2 * j]);
        acc[2 * j + 1] = fmaf(w, f.y, acc[2 * j + 1]);
    }
}

__global__ __launch_bounds__(256) void gather1(const float* __restrict__ b1) {
    gdc_launch_dependents();   // let gemm2 blocks stage W2 early
    const int n = (blockIdx.x * blockDim.x + threadIdx.x) >> 5;
    const int lane = threadIdx.x & 31;

    // prologue independent of gemm1 output
    float acc[8];
    {
        const float4 blo = __ldg((const float4*)b1 + lane * 2);
        const float4 bhi = __ldg((const float4*)b1 + lane * 2 + 1);
        acc[0] = blo.x; acc[1] = blo.y; acc[2] = blo.z; acc[3] = blo.w;
        acc[4] = bhi.x; acc[5] = bhi.y; acc[6] = bhi.z; acc[7] = bhi.w;
    }
    gdc_wait();                // s1h (gemm1 output) safe to read after this

    const int beg = g_off[n];
    const int end = g_off[n + 1];

    int e = beg;
    for (; e + 7 < end; e += 8) {
        int2 c[8];
        uint4 v[8];
        #pragma unroll
        for (int i = 0; i < 8; i++) c[i] = __ldcs(&g_csr[e + i]);
        #pragma unroll
        for (int i = 0; i < 8; i++)
            v[i] = __ldg((const uint4*)(g_s1h + (size_t)c[i].x * F_HID) + lane);
        #pragma unroll
        for (int i = 0; i < 8; i++) accum8(acc, v[i], __int_as_float(c[i].y));
    }
    for (; e < end; e++) {
        const int2 c = __ldcs(&g_csr[e]);
        const uint4 v = __ldg((const uint4*)(g_s1h + (size_t)c.x * F_HID) + lane);
        accum8(acc, v, __int_as_float(c.y));
    }

    uint4 o;
    __half2* ph = (__half2*)&o;
    #pragma unroll
    for (int j = 0; j < 4; j++)
        ph[j] = __floats2half2_rn(fmaxf(acc[2 * j], 0.f), fmaxf(acc[2 * j + 1], 0.f));
    __stcs((uint4*)(g_h1h + (size_t)n * F_HID) + lane, o);
}

// ====== gemm2: support2 = a1 @ W2 (fp16 mma; W2 fragments via smem) =========
#define G2_NT 5
__global__ __launch_bounds__(256) void gemm2_mma() {
    __shared__ __align__(16) uint32_t Wf[16 * G2_NT * 32 * 2];   // 10 KB

    gdc_launch_dependents();   // let gather2 blocks start early

    const int tid = threadIdx.x;
    // prologue: stage W2 fragments (independent of gather1 output)
    for (int i = tid; i < (16 * G2_NT * 32 * 2) / 4; i += 256)
        ((uint4*)Wf)[i] = ((const uint4*)g_w2f)[i];
    __syncthreads();

    gdc_wait();                // h1h (gather1 output) safe to read after this

    const int lane = tid & 31, warp = tid >> 5;
    const int node0 = blockIdx.x * 128 + warp * 16 + (lane >> 2);
    const int node1 = node0 + 8;
    const bool v0 = node0 < N_NODES, v1 = node1 < N_NODES;

    float acc[G2_NT][4];
    #pragma unroll
    for (int nt = 0; nt < G2_NT; nt++)
        #pragma unroll
        for (int r = 0; r < 4; r++) acc[nt][r] = 0.f;

    const __half* r0 = g_h1h + (size_t)node0 * F_HID;
    const __half* r1 = g_h1h + (size_t)node1 * F_HID;

    #pragma unroll
    for (int kt = 0; kt < 16; kt++) {
        const int kof = kt * 16 + (lane & 3) * 2;
        uint32_t a[4];
        a[0] = v0 ? __ldg((const uint32_t*)(r0 + kof))     : 0u;
        a[1] = v1 ? __ldg((const uint32_t*)(r1 + kof))     : 0u;
        a[2] = v0 ? __ldg((const uint32_t*)(r0 + kof + 8)) : 0u;
        a[3] = v1 ? __ldg((const uint32_t*)(r1 + kof + 8)) : 0u;
        #pragma unroll
        for (int nt = 0; nt < G2_NT; nt++) {
            const uint32_t* bp = &Wf[(((size_t)kt * G2_NT + nt) * 32 + lane) * 2];
            const uint32_t b[2] = {bp[0], bp[1]};
            mma_f16(acc[nt], a, b);
        }
    }

    const int col = (lane & 3) * 2;
    #pragma unroll
    for (int nt = 0; nt < G2_NT; nt++) {
        if (v0)
            *(__half2*)(g_s2h + (size_t)node0 * F_OUT + nt * 8 + col) =
                __floats2half2_rn(acc[nt][0], acc[nt][1]);
        if (v1)
            *(__half2*)(g_s2h + (size_t)node1 * F_OUT + nt * 8 + col) =
                __floats2half2_rn(acc[nt][2], acc[nt][3]);
    }
}

// ========== layer-2 gather + log_softmax: warp/node, 3 edge-slots ==========
__global__ __launch_bounds__(256) void gather2_softmax(const float* __restrict__ b2,
                                                       float* __restrict__ out) {
    const int n = (blockIdx.x * blockDim.x + threadIdx.x) >> 5;
    const int lane = threadIdx.x & 31;
    const int slot = lane / 10;          // 0,1,2 (3 for lanes 30,31)
    const int pos  = lane - slot * 10;   // 0..9
    const bool act = lane < 30;

    const int beg = g_off[n];
    const int end = g_off[n + 1];

    float acc[4] = {0.f, 0.f, 0.f, 0.f};

    gdc_wait();                // s2h (gemm2 output) safe to read after this

    const int total = end - beg;
    int base = 0;
    for (; base + 6 <= total; base += 6) {
        const int e0 = beg + base + slot;
        const int e1 = e0 + 3;
        int2 c0, c1;
        uint2 v0, v1;
        if (act) {
            c0 = __ldcs(&g_csr[e0]);
            c1 = __ldcs(&g_csr[e1]);
            v0 = __ldg((const uint2*)(g_s2h + (size_t)c0.x * F_OUT) + pos);
            v1 = __ldg((const uint2*)(g_s2h + (size_t)c1.x * F_OUT) + pos);
            const float w0 = __int_as_float(c0.y);
            const float w1 = __int_as_float(c1.y);
            const __half2* h0 = (const __half2*)&v0;
            const __half2* h1 = (const __half2*)&v1;
            const float2 a0 = __half22float2(h0[0]), a1 = __half22float2(h0[1]);
            const float2 b0 = __half22float2(h1[0]), b1 = __half22float2(h1[1]);
            acc[0] = fmaf(w0, a0.x, acc[0]); acc[1] = fmaf(w0, a0.y, acc[1]);
            acc[2] = fmaf(w0, a1.x, acc[2]); acc[3] = fmaf(w0, a1.y, acc[3]);
            acc[0] = fmaf(w1, b0.x, acc[0]); acc[1] = fmaf(w1, b0.y, acc[1]);
            acc[2] = fmaf(w1, b1.x, acc[2]); acc[3] = fmaf(w1, b1.y, acc[3]);
        }
    }
    for (; base < total; base += 3) {
        const int e = beg + base + slot;
        if (act && e < end) {
            const int2 c = __ldcs(&g_csr[e]);
            const uint2 v = __ldg((const uint2*)(g_s2h + (size_t)c.x * F_OUT) + pos);
            const float w = __int_as_float(c.y);
            const __half2* h = (const __half2*)&v;
            const float2 f0 = __half22float2(h[0]), f1 = __half22float2(h[1]);
            acc[0] = fmaf(w, f0.x, acc[0]); acc[1] = fmaf(w, f0.y, acc[1]);
            acc[2] = fmaf(w, f1.x, acc[2]); acc[3] = fmaf(w, f1.y, acc[3]);
        }
    }

    // combine the 3 slots: feature group p lives at lanes p, p+10, p+20
    #pragma unroll
    for (int j = 0; j < 4; j++) {
        const float a10 = __shfl_sync(0xffffffffu, acc[j], pos + 10);
        const float a20 = __shfl_sync(0xffffffffu, acc[j], pos + 20);
        acc[j] += a10 + a20;
    }

    const bool own = lane < 10;
    if (own) {
        const float4 b = __ldg((const float4*)b2 + lane);
        acc[0] += b.x; acc[1] += b.y; acc[2] += b.z; acc[3] += b.w;
    }

    const float NEG_INF = __int_as_float(0xff800000);
    float m = own ? fmaxf(fmaxf(acc[0], acc[1]), fmaxf(acc[2], acc[3])) : NEG_INF;
    #pragma unroll
    for (int o = 16; o > 0; o >>= 1)
        m = fmaxf(m, __shfl_xor_sync(0xffffffffu, m, o));
    float s = own ? (expf(acc[0] - m) + expf(acc[1] - m) +
                     expf(acc[2] - m) + expf(acc[3] - m)) : 0.f;
    #pragma unroll
    for (int o = 16; o > 0; o >>= 1)
        s += __shfl_xor_sync(0xffffffffu, s, o);
    const float l = m + logf(s);

    if (own) {
        const float4 o4 = make_float4(acc[0] - l, acc[1] - l, acc[2] - l, acc[3] - l);
        *((float4*)(out + (size_t)n * F_OUT) + lane) = o4;
    }
}

// ---------------- launch ----------------------------------------------------
template <typename... Args>
static void launch_pdl(void (*k)(Args...), dim3 grid, dim3 block, Args... args) {
    cudaLaunchConfig_t cfg = {};
    cfg.gridDim = grid; cfg.blockDim = block; cfg.stream = 0;
    cudaLaunchAttribute attr[1];
    attr[0].id = cudaLaunchAttributeProgrammaticStreamSerialization;
    attr[0].val.programmaticStreamSerializationAllowed = 1;
    cfg.attrs = attr; cfg.numAttrs = 1;
    cudaLaunchKernelEx(&cfg, k, args...);
}

extern "C" void kernel_launch(void* const* d_in, const int* in_sizes, int n_in,
                              void* d_out, int out_size) {
    const float* x   = (const float*)d_in[0];
    const int*   ei  = (const int*)d_in[1];
    const float* ew  = (const float*)d_in[2];
    const float* W1  = (const float*)d_in[3];
    const float* b1  = (const float*)d_in[4];
    const float* W2  = (const float*)d_in[5];
    const float* b2  = (const float*)d_in[6];
    float* out = (float*)d_out;

    const int E = in_sizes[2];
    const int* src = ei;
    const int* dst = ei + E;

    // Fork: CSR build + W2 pack run concurrently with W1 pack + gemm1.
    cudaStream_t s2;
    cudaStreamCreate(&s2);
    cudaEvent_t evFork, evJoin;
    cudaEventCreateWithFlags(&evFork, cudaEventDisableTiming);
    cudaEventCreateWithFlags(&evJoin, cudaEventDisableTiming);

    cudaEventRecord(evFork, 0);
    cudaStreamWaitEvent(s2, evFork, 0);

    // branch A (main stream): pack W1, then support1 = x @ W1 (PDL-chained)
    pack_W1<<<128, 256>>>(W1);
    launch_pdl(gemm1_f16, dim3(2, (N_NODES + G1_BM - 1) / G1_BM), dim3(256),
               x, (int)N_NODES);

    // branch B (side stream): W2 pack + CSR build
    {
        const int nb = (N_NODES + 255) / 256;
        const int eb = (E + 255) / 256;
        pack_W2<<<10, 256, 0, s2>>>(W2);
        hist_dst<<<eb, 256, 0, s2>>>(dst, E);
        scan_block<<<SCAN_NB, SCAN_B, 0, s2>>>();
        scan_top<<<1, 256, 0, s2>>>();
        scan_add<<<nb, 256, 0, s2>>>(E);
        fill_csr<<<eb, 256, 0, s2>>>(src, dst, ew, E);
    }

    cudaEventRecord(evJoin, s2);
    cudaStreamWaitEvent(0, evJoin, 0);

    // layer-1 gather (PDL: prologue + ramp overlap gemm1 epilogue/drain)
    launch_pdl(gather1, dim3((N_NODES * 32 + 255) / 256), dim3(256), b1);
    // support2 = a1 @ W2 (PDL: W2 smem staging overlaps gather1 straggler drain)
    launch_pdl(gemm2_mma, dim3((N_NODES + 127) / 128), dim3(256));
    // out = log_softmax(b2 + gather(ew * support2[src])) (PDL: overlaps gemm2 drain)
    launch_pdl(gather2_softmax, dim3((N_NODES * 32 + 255) / 256), dim3(256), b2, out);

    cudaStreamDestroy(s2);
    cudaEventDestroy(evFork);
    cudaEventDestroy(evJoin);
}

// round 16
// speedup vs baseline: 1.1600x; 1.0084x over previous
#include <cuda_runtime.h>
#include <cuda_fp16.h>
#include <cstdint>

#define N_NODES 100000
#define F_IN    512
#define F_HID   256
#define F_OUT   40
#define E_MAX   3200000

#define SCAN_B  512
#define SCAN_NB ((N_NODES + SCAN_B - 1) / SCAN_B)   // 196

// ---------------- scratch (device globals; no allocation allowed) ----------
__device__ __align__(128) __half g_s1h[(size_t)N_NODES * F_HID];   // 51.2 MB
__device__ __align__(128) __half g_h1h[(size_t)N_NODES * F_HID];   // 51.2 MB
__device__ __align__(128) __half g_s2h[(size_t)N_NODES * F_OUT];   // 8 MB

// W1 pre-packed into mma B-fragment order: [kt(32)][nt(32)][lane(32)][2]
__device__ __align__(16) uint32_t g_w1f[32 * 32 * 32 * 2];          // 256 KB
// W2 pre-packed fragments: [kt(16)][nt(5)][lane(32)][2]
__device__ __align__(16) uint32_t g_w2f[16 * 5 * 32 * 2];           // 10 KB

__device__ int  g_cnt[N_NODES];          // zero at module load; re-zeroed by scan_add
__device__ int  g_off[N_NODES + 1];      // +1 sentinel = E
__device__ int  g_pos[N_NODES];
__device__ int  g_blksum[SCAN_NB];
__device__ __align__(16) int2 g_csr[E_MAX];    // (src, float-bits of w)

// ---------------- PDL helpers (no-ops when attr not set) --------------------
__device__ __forceinline__ void gdc_wait() {
    asm volatile("griddepcontrol.wait;" ::: "memory");
}
__device__ __forceinline__ void gdc_launch_dependents() {
    asm volatile("griddepcontrol.launch_dependents;");
}

// ---------------- fp16 mma helper -------------------------------------------
__device__ __forceinline__ void mma_f16(float* c, const uint32_t* a, const uint32_t* b) {
    asm volatile("mma.sync.aligned.m16n8k16.row.col.f32.f16.f16.f32 "
                 "{%0,%1,%2,%3}, {%4,%5,%6,%7}, {%8,%9}, {%0,%1,%2,%3};"
                 : "+f"(c[0]), "+f"(c[1]), "+f"(c[2]), "+f"(c[3])
                 : "r"(a[0]), "r"(a[1]), "r"(a[2]), "r"(a[3]),
                   "r"(b[0]), "r"(b[1]));
}

// ================ pack W1 (fp32 [512,256]) into fragment order ===============
__global__ void pack_W1(const float* __restrict__ W1) {
    gdc_launch_dependents();   // gemm1 may start its A-prologue immediately
    const int idx = blockIdx.x * blockDim.x + threadIdx.x;   // 0..32767
    if (idx >= 32 * 32 * 32) return;
    const int kt = idx >> 10;
    const int rem = idx & 1023;
    const int nt = rem >> 5;
    const int ln = rem & 31;
    const int n = nt * 8 + (ln >> 2);
    const int k = kt * 16 + (ln & 3) * 2;
    const __half2 h0 = __floats2half2_rn(W1[(size_t)k * F_HID + n],
                                         W1[(size_t)(k + 1) * F_HID + n]);
    const __half2 h1 = __floats2half2_rn(W1[(size_t)(k + 8) * F_HID + n],
                                         W1[(size_t)(k + 9) * F_HID + n]);
    g_w1f[idx * 2]     = *(const uint32_t*)&h0;
    g_w1f[idx * 2 + 1] = *(const uint32_t*)&h1;
}

// ================ pack W2 (fp32 [256,40]) into fragment order ================
__global__ void pack_W2(const float* __restrict__ W2) {
    const int idx = blockIdx.x * blockDim.x + threadIdx.x;   // 0..2559
    if (idx >= 16 * 5 * 32) return;
    const int kt = idx / (5 * 32);
    const int rem = idx % (5 * 32);
    const int nt = rem / 32;
    const int ln = rem % 32;
    const int n = nt * 8 + (ln >> 2);
    const int k0 = kt * 16 + (ln & 3) * 2;
    const __half2 h0 = __floats2half2_rn(W2[(size_t)k0 * F_OUT + n],
                                         W2[(size_t)(k0 + 1) * F_OUT + n]);
    const __half2 h1 = __floats2half2_rn(W2[(size_t)(k0 + 8) * F_OUT + n],
                                         W2[(size_t)(k0 + 9) * F_OUT + n]);
    g_w2f[idx * 2]     = *(const uint32_t*)&h0;
    g_w2f[idx * 2 + 1] = *(const uint32_t*)&h1;
}

// ================= gemm1: support1 = x @ W1  (fp16 MMA, fp16 out) ==========
// Block tile 64(M) x 128(N) x 32(K); 8 warps, warp tile 32x32.
// 3 CTAs/SM (~76 regs) for latency hiding; A fill is one STS.128/thread.
#define G1_BM 64
#define G1_BK 32
#define AS_PAD 36

__global__ __launch_bounds__(256, 3) void gemm1_f16(const float* __restrict__ A, int M) {
    __shared__ __align__(16) uint32_t As[2][4][8][AS_PAD];   // 9.2 KB

    const int tid  = threadIdx.x;
    const int lane = tid & 31;
    const int warp = tid >> 5;
    const int wm = warp & 1;      // 0..1 -> 32-row slab (2 mtiles)
    const int wn = warp >> 1;     // 0..3 -> 32-col slab (4 ntiles)
    const int rowBase = blockIdx.y * G1_BM;
    const int ntBase  = blockIdx.x * 16;   // 16 n-tiles (128 cols) per block

    // A fill: row = tid/4 (0..63), k-octet = (tid&3)*8
    const int ar  = tid >> 2;
    const int k0  = (tid & 3) * 8;
    const int amt = ar >> 4, arr = ar & 15;
    // fragment slot for this thread's k-octet
    const int regslot = ((k0 >> 4) * 4) + (arr >> 3) + 2 * ((k0 >> 3) & 1);
    const int l0 = (arr & 7) * 4;

    float acc[2][4][4];
    #pragma unroll
    for (int mt = 0; mt < 2; mt++)
        #pragma unroll
        for (int nt = 0; nt < 4; nt++)
            #pragma unroll
            for (int r = 0; r < 4; r++) acc[mt][nt][r] = 0.f;

    const int arow = rowBase + ar;
    const float* Arow = A + (size_t)arow * F_IN + k0;
    float4 pa[2];

    // prologue: A tile 0 (independent of pack_W1 output)
    {
        pa[0] = (arow < M) ? __ldcs((const float4*)(Arow))     : make_float4(0.f, 0.f, 0.f, 0.f);
        pa[1] = (arow < M) ? __ldcs((const float4*)(Arow + 4)) : make_float4(0.f, 0.f, 0.f, 0.f);
        const float* f = (const float*)pa;
        uint4 st;
        uint32_t* ps = (uint32_t*)&st;
        #pragma unroll
        for (int j = 0; j < 4; j++) {
            const __half2 h = __floats2half2_rn(f[2 * j], f[2 * j + 1]);
            ps[j] = *(const uint32_t*)&h;
        }
        *(uint4*)&As[0][amt][regslot][l0] = st;
    }
    __syncthreads();

    gdc_wait();   // g_w1f (pack_W1 output) safe to read after this

    const int NT = F_IN / G1_BK;   // 16
    for (int t = 0; t < NT; t++) {
        const int buf = t & 1;
        if (t + 1 < NT) {
            const float* Anext = Arow + (t + 1) * G1_BK;
            pa[0] = (arow < M) ? __ldcs((const float4*)(Anext))     : make_float4(0.f, 0.f, 0.f, 0.f);
            pa[1] = (arow < M) ? __ldcs((const float4*)(Anext + 4)) : make_float4(0.f, 0.f, 0.f, 0.f);
        }

        #pragma unroll
        for (int ks = 0; ks < 2; ks++) {
            const int kt = t * 2 + ks;
            uint32_t bfr[4][2];
            #pragma unroll
            for (int nt = 0; nt < 4; nt++) {
                const uint2 v = __ldg((const uint2*)
                    &g_w1f[(((size_t)kt * 32 + ntBase + wn * 4 + nt) * 32 + lane) * 2]);
                bfr[nt][0] = v.x; bfr[nt][1] = v.y;
            }
            uint32_t afr[2][4];
            #pragma unroll
            for (int mt = 0; mt < 2; mt++)
                #pragma unroll
                for (int r = 0; r < 4; r++)
                    afr[mt][r] = As[buf][wm * 2 + mt][ks * 4 + r][lane];
            #pragma unroll
            for (int mt = 0; mt < 2; mt++)
                #pragma unroll
                for (int nt = 0; nt < 4; nt++)
                    mma_f16(acc[mt][nt], afr[mt], bfr[nt]);
        }

        if (t + 1 < NT) {
            const int nb = buf ^ 1;
            const float* f = (const float*)pa;
            uint4 st;
            uint32_t* ps = (uint32_t*)&st;
            #pragma unroll
            for (int j = 0; j < 4; j++) {
                const __half2 h = __floats2half2_rn(f[2 * j], f[2 * j + 1]);
                ps[j] = *(const uint32_t*)&h;
            }
            *(uint4*)&As[nb][amt][regslot][l0] = st;
        }
        __syncthreads();
    }

    gdc_launch_dependents();   // let gather1 ramp during the epilogue/drain

    #pragma unroll
    for (int mt = 0; mt < 2; mt++) {
        const int row0 = rowBase + wm * 32 + mt * 16 + (lane >> 2);
        #pragma unroll
        for (int nt = 0; nt < 4; nt++) {
            const int col = (ntBase + wn * 4 + nt) * 8 + (lane & 3) * 2;
            if (row0 < M)
                *(__half2*)(g_s1h + (size_t)row0 * F_HID + col) =
                    __floats2half2_rn(acc[mt][nt][0], acc[mt][nt][1]);
            if (row0 + 8 < M)
                *(__half2*)(g_s1h + (size_t)(row0 + 8) * F_HID + col) =
                    __floats2half2_rn(acc[mt][nt][2], acc[mt][nt][3]);
        }
    }
}

// ================= CSR build =================================================
__global__ void hist_dst(const int* __restrict__ dst, int E) {
    const int e = blockIdx.x * blockDim.x + threadIdx.x;
    if (e < E) atomicAdd(&g_cnt[__ldcs(dst + e)], 1);
}

__global__ void scan_block() {
    __shared__ int sh[SCAN_B];
    const int t = threadIdx.x;
    const int i = blockIdx.x * SCAN_B + t;
    const int v = (i < N_NODES) ? g_cnt[i] : 0;
    sh[t] = v;
    __syncthreads();
    #pragma unroll
    for (int o = 1; o < SCAN_B; o <<= 1) {
        int x = 0;
        if (t >= o) x = sh[t - o];
        __syncthreads();
        sh[t] += x;
        __syncthreads();
    }
    if (i < N_NODES) g_off[i] = sh[t] - v;
    if (t == SCAN_B - 1) g_blksum[blockIdx.x] = sh[t];
}

__global__ void scan_top() {
    __shared__ int sh[256];
    const int t = threadIdx.x;
    const int v = (t < SCAN_NB) ? g_blksum[t] : 0;
    sh[t] = v;
    __syncthreads();
    #pragma unroll
    for (int o = 1; o < 256; o <<= 1) {
        int x = 0;
        if (t >= o) x = sh[t - o];
        __syncthreads();
        sh[t] += x;
        __syncthreads();
    }
    if (t < SCAN_NB) g_blksum[t] = sh[t] - v;
}

// also re-zeroes g_cnt for the next graph replay and writes the sentinel
__global__ void scan_add(int E) {
    const int i = blockIdx.x * blockDim.x + threadIdx.x;
    if (i < N_NODES) {
        const int o = g_off[i] + g_blksum[i / SCAN_B];
        g_off[i] = o;
        g_pos[i] = o;
        g_cnt[i] = 0;
    }
    if (i == 0) g_off[N_NODES] = E;
}

__global__ void fill_csr(const int* __restrict__ src, const int* __restrict__ dst,
                         const float* __restrict__ ew, int E) {
    const int e = blockIdx.x * blockDim.x + threadIdx.x;
    if (e < E) {
        const int p = atomicAdd(&g_pos[__ldcs(dst + e)], 1);
        __stcs(&g_csr[p], make_int2(__ldcs(src + e), __float_as_int(__ldcs(ew + e))));
    }
}

// ======== layer-1 gather: warp per node, full 256 feats (fp16 rows) =========
__device__ __forceinline__ void accum8(float* acc, uint4 v, float w) {
    const __half2* h = (const __half2*)&v;
    #pragma unroll
    for (int j = 0; j < 4; j++) {
        const float2 f = __half22float2(h[j]);
        acc[2 * j]     = fmaf(w, f.x, acc[2 * j]);
        acc[2 * j + 1] = fmaf(w, f.y, acc[2 * j + 1]);
    }
}

__global__ __launch_bounds__(256) void gather1(const float* __restrict__ b1) {
    gdc_launch_dependents();   // let gemm2 blocks stage W2 early
    const int n = (blockIdx.x * blockDim.x + threadIdx.x) >> 5;
    const int lane = threadIdx.x & 31;

    // prologue independent of gemm1 output
    float acc[8];
    {
        const float4 blo = __ldg((const float4*)b1 + lane * 2);
        const float4 bhi = __ldg((const float4*)b1 + lane * 2 + 1);
        acc[0] = blo.x; acc[1] = blo.y; acc[2] = blo.z; acc[3] = blo.w;
        acc[4] = bhi.x; acc[5] = bhi.y; acc[6] = bhi.z; acc[7] = bhi.w;
    }
    gdc_wait();                // s1h (gemm1 output) safe to read after this

    const int beg = g_off[n];
    const int end = g_off[n + 1];

    int e = beg;
    for (; e + 7 < end; e += 8) {
        int2 c[8];
        uint4 v[8];
        #pragma unroll
        for (int i = 0; i < 8; i++) c[i] = __ldcs(&g_csr[e + i]);
        #pragma unroll
        for (int i = 0; i < 8; i++)
            v[i] = __ldg((const uint4*)(g_s1h + (size_t)c[i].x * F_HID) + lane);
        #pragma unroll
        for (int i = 0; i < 8; i++) accum8(acc, v[i], __int_as_float(c[i].y));
    }
    for (; e < end; e++) {
        const int2 c = __ldcs(&g_csr[e]);
        const uint4 v = __ldg((const uint4*)(g_s1h + (size_t)c.x * F_HID) + lane);
        accum8(acc, v, __int_as_float(c.y));
    }

    uint4 o;
    __half2* ph = (__half2*)&o;
    #pragma unroll
    for (int j = 0; j < 4; j++)
        ph[j] = __floats2half2_rn(fmaxf(acc[2 * j], 0.f), fmaxf(acc[2 * j + 1], 0.f));
    __stcs((uint4*)(g_h1h + (size_t)n * F_HID) + lane, o);
}

// ====== gemm2: support2 = a1 @ W2 (fp16 mma; W2 fragments via smem) =========
#define G2_NT 5
__global__ __launch_bounds__(256) void gemm2_mma() {
    __shared__ __align__(16) uint32_t Wf[16 * G2_NT * 32 * 2];   // 10 KB

    gdc_launch_dependents();   // let gather2 blocks start early

    const int tid = threadIdx.x;
    // prologue: stage W2 fragments (independent of gather1 output)
    for (int i = tid; i < (16 * G2_NT * 32 * 2) / 4; i += 256)
        ((uint4*)Wf)[i] = ((const uint4*)g_w2f)[i];
    __syncthreads();

    gdc_wait();                // h1h (gather1 output) safe to read after this

    const int lane = tid & 31, warp = tid >> 5;
    const int node0 = blockIdx.x * 128 + warp * 16 + (lane >> 2);
    const int node1 = node0 + 8;
    const bool v0 = node0 < N_NODES, v1 = node1 < N_NODES;

    float acc[G2_NT][4];
    #pragma unroll
    for (int nt = 0; nt < G2_NT; nt++)
        #pragma unroll
        for (int r = 0; r < 4; r++) acc[nt][r] = 0.f;

    const __half* r0 = g_h1h + (size_t)node0 * F_HID;
    const __half* r1 = g_h1h + (size_t)node1 * F_HID;

    #pragma unroll
    for (int kt = 0; kt < 16; kt++) {
        const int kof = kt * 16 + (lane & 3) * 2;
        uint32_t a[4];
        a[0] = v0 ? __ldg((const uint32_t*)(r0 + kof))     : 0u;
        a[1] = v1 ? __ldg((const uint32_t*)(r1 + kof))     : 0u;
        a[2] = v0 ? __ldg((const uint32_t*)(r0 + kof + 8)) : 0u;
        a[3] = v1 ? __ldg((const uint32_t*)(r1 + kof + 8)) : 0u;
        #pragma unroll
        for (int nt = 0; nt < G2_NT; nt++) {
            const uint32_t* bp = &Wf[(((size_t)kt * G2_NT + nt) * 32 + lane) * 2];
            const uint32_t b[2] = {bp[0], bp[1]};
            mma_f16(acc[nt], a, b);
        }
    }

    const int col = (lane & 3) * 2;
    #pragma unroll
    for (int nt = 0; nt < G2_NT; nt++) {
        if (v0)
            *(__half2*)(g_s2h + (size_t)node0 * F_OUT + nt * 8 + col) =
                __floats2half2_rn(acc[nt][0], acc[nt][1]);
        if (v1)
            *(__half2*)(g_s2h + (size_t)node1 * F_OUT + nt * 8 + col) =
                __floats2half2_rn(acc[nt][2], acc[nt][3]);
    }
}

// ========== layer-2 gather + log_softmax: warp/node, 3 edge-slots ==========
__global__ __launch_bounds__(256) void gather2_softmax(const float* __restrict__ b2,
                                                       float* __restrict__ out) {
    const int n = (blockIdx.x * blockDim.x + threadIdx.x) >> 5;
    const int lane = threadIdx.x & 31;
    const int slot = lane / 10;          // 0,1,2 (3 for lanes 30,31)
    const int pos  = lane - slot * 10;   // 0..9
    const bool act = lane < 30;

    const int beg = g_off[n];
    const int end = g_off[n + 1];

    float acc[4] = {0.f, 0.f, 0.f, 0.f};

    gdc_wait();                // s2h (gemm2 output) safe to read after this

    const int total = end - beg;
    int base = 0;
    for (; base + 6 <= total; base += 6) {
        const int e0 = beg + base + slot;
        const int e1 = e0 + 3;
        int2 c0, c1;
        uint2 v0, v1;
        if (act) {
            c0 = __ldcs(&g_csr[e0]);
            c1 = __ldcs(&g_csr[e1]);
            v0 = __ldg((const uint2*)(g_s2h + (size_t)c0.x * F_OUT) + pos);
            v1 = __ldg((const uint2*)(g_s2h + (size_t)c1.x * F_OUT) + pos);
            const float w0 = __int_as_float(c0.y);
            const float w1 = __int_as_float(c1.y);
            const __half2* h0 = (const __half2*)&v0;
            const __half2* h1 = (const __half2*)&v1;
            const float2 a0 = __half22float2(h0[0]), a1 = __half22float2(h0[1]);
            const float2 b0 = __half22float2(h1[0]), b1 = __half22float2(h1[1]);
            acc[0] = fmaf(w0, a0.x, acc[0]); acc[1] = fmaf(w0, a0.y, acc[1]);
            acc[2] = fmaf(w0, a1.x, acc[2]); acc[3] = fmaf(w0, a1.y, acc[3]);
            acc[0] = fmaf(w1, b0.x, acc[0]); acc[1] = fmaf(w1, b0.y, acc[1]);
            acc[2] = fmaf(w1, b1.x, acc[2]); acc[3] = fmaf(w1, b1.y, acc[3]);
        }
    }
    for (; base < total; base += 3) {
        const int e = beg + base + slot;
        if (act && e < end) {
            const int2 c = __ldcs(&g_csr[e]);
            const uint2 v = __ldg((const uint2*)(g_s2h + (size_t)c.x * F_OUT) + pos);
            const float w = __int_as_float(c.y);
            const __half2* h = (const __half2*)&v;
            const float2 f0 = __half22float2(h[0]), f1 = __half22float2(h[1]);
            acc[0] = fmaf(w, f0.x, acc[0]); acc[1] = fmaf(w, f0.y, acc[1]);
            acc[2] = fmaf(w, f1.x, acc[2]); acc[3] = fmaf(w, f1.y, acc[3]);
        }
    }

    // combine the 3 slots: feature group p lives at lanes p, p+10, p+20
    #pragma unroll
    for (int j = 0; j < 4; j++) {
        const float a10 = __shfl_sync(0xffffffffu, acc[j], pos + 10);
        const float a20 = __shfl_sync(0xffffffffu, acc[j], pos + 20);
        acc[j] += a10 + a20;
    }

    const bool own = lane < 10;
    if (own) {
        const float4 b = __ldg((const float4*)b2 + lane);
        acc[0] += b.x; acc[1] += b.y; acc[2] += b.z; acc[3] += b.w;
    }

    const float NEG_INF = __int_as_float(0xff800000);
    float m = own ? fmaxf(fmaxf(acc[0], acc[1]), fmaxf(acc[2], acc[3])) : NEG_INF;
    #pragma unroll
    for (int o = 16; o > 0; o >>= 1)
        m = fmaxf(m, __shfl_xor_sync(0xffffffffu, m, o));
    float s = own ? (expf(acc[0] - m) + expf(acc[1] - m) +
                     expf(acc[2] - m) + expf(acc[3] - m)) : 0.f;
    #pragma unroll
    for (int o = 16; o > 0; o >>= 1)
        s += __shfl_xor_sync(0xffffffffu, s, o);
    const float l = m + logf(s);

    if (own) {
        const float4 o4 = make_float4(acc[0] - l, acc[1] - l, acc[2] - l, acc[3] - l);
        *((float4*)(out + (size_t)n * F_OUT) + lane) = o4;
    }
}

// ---------------- launch ----------------------------------------------------
template <typename... Args>
static void launch_pdl(void (*k)(Args...), dim3 grid, dim3 block, Args... args) {
    cudaLaunchConfig_t cfg = {};
    cfg.gridDim = grid; cfg.blockDim = block; cfg.stream = 0;
    cudaLaunchAttribute attr[1];
    attr[0].id = cudaLaunchAttributeProgrammaticStreamSerialization;
    attr[0].val.programmaticStreamSerializationAllowed = 1;
    cfg.attrs = attr; cfg.numAttrs = 1;
    cudaLaunchKernelEx(&cfg, k, args...);
}

extern "C" void kernel_launch(void* const* d_in, const int* in_sizes, int n_in,
                              void* d_out, int out_size) {
    const float* x   = (const float*)d_in[0];
    const int*   ei  = (const int*)d_in[1];
    const float* ew  = (const float*)d_in[2];
    const float* W1  = (const float*)d_in[3];
    const float* b1  = (const float*)d_in[4];
    const float* W2  = (const float*)d_in[5];
    const float* b2  = (const float*)d_in[6];
    float* out = (float*)d_out;

    const int E = in_sizes[2];
    const int* src = ei;
    const int* dst = ei + E;

    // Fork: CSR build + W2 pack run concurrently with W1 pack + gemm1.
    cudaStream_t s2;
    cudaStreamCreate(&s2);
    cudaEvent_t evFork, evJoin;
    cudaEventCreateWithFlags(&evFork, cudaEventDisableTiming);
    cudaEventCreateWithFlags(&evJoin, cudaEventDisableTiming);

    cudaEventRecord(evFork, 0);
    cudaStreamWaitEvent(s2, evFork, 0);

    // branch A (main stream): pack W1, then support1 = x @ W1 (PDL-chained)
    pack_W1<<<128, 256>>>(W1);
    launch_pdl(gemm1_f16, dim3(2, (N_NODES + G1_BM - 1) / G1_BM), dim3(256),
               x, (int)N_NODES);

    // branch B (side stream): W2 pack + CSR build
    {
        const int nb = (N_NODES + 255) / 256;
        const int eb = (E + 255) / 256;
        pack_W2<<<10, 256, 0, s2>>>(W2);
        hist_dst<<<eb, 256, 0, s2>>>(dst, E);
        scan_block<<<SCAN_NB, SCAN_B, 0, s2>>>();
        scan_top<<<1, 256, 0, s2>>>();
        scan_add<<<nb, 256, 0, s2>>>(E);
        fill_csr<<<eb, 256, 0, s2>>>(src, dst, ew, E);
    }

    cudaEventRecord(evJoin, s2);
    cudaStreamWaitEvent(0, evJoin, 0);

    // layer-1 gather (PDL: prologue + ramp overlap gemm1 epilogue/drain)
    launch_pdl(gather1, dim3((N_NODES * 32 + 255) / 256), dim3(256), b1);
    // support2 = a1 @ W2 (PDL: W2 smem staging overlaps gather1 straggler drain)
    launch_pdl(gemm2_mma, dim3((N_NODES + 127) / 128), dim3(256));
    // out = log_softmax(b2 + gather(ew * support2[src])) (PDL: overlaps gemm2 drain)
    launch_pdl(gather2_softmax, dim3((N_NODES * 32 + 255) / 256), dim3(256), b2, out);

    cudaStreamDestroy(s2);
    cudaEventDestroy(evFork);
    cudaEventDestroy(evJoin);
}

// round 17
// speedup vs baseline: 1.1613x; 1.0012x over previous
#include <cuda_runtime.h>
#include <cuda_fp16.h>
#include <cstdint>

#define N_NODES 100000
#define F_IN    512
#define F_HID   256
#define F_OUT   40
#define E_MAX   3200000

#define SCAN_B  512
#define SCAN_NB ((N_NODES + SCAN_B - 1) / SCAN_B)   // 196

// ---------------- scratch (device globals; no allocation allowed) ----------
__device__ __align__(128) __half g_s1h[(size_t)N_NODES * F_HID];   // 51.2 MB
__device__ __align__(128) __half g_h1h[(size_t)N_NODES * F_HID];   // 51.2 MB
__device__ __align__(128) __half g_s2h[(size_t)N_NODES * F_OUT];   // 8 MB

// W1 pre-packed into mma B-fragment order: [kt(32)][nt(32)][lane(32)][2]
__device__ __align__(16) uint32_t g_w1f[32 * 32 * 32 * 2];          // 256 KB
// W2 pre-packed fragments: [kt(16)][nt(5)][lane(32)][2]
__device__ __align__(16) uint32_t g_w2f[16 * 5 * 32 * 2];           // 10 KB

__device__ int  g_cnt[N_NODES];          // zero at module load; re-zeroed by scan_add
__device__ int  g_off[N_NODES + 1];      // +1 sentinel = E
__device__ int  g_pos[N_NODES];
__device__ int  g_blksum[SCAN_NB];
__device__ __align__(16) int2 g_csr[E_MAX];    // (src, float-bits of w)

// ---------------- PDL helpers (no-ops when attr not set) --------------------
__device__ __forceinline__ void gdc_wait() {
    asm volatile("griddepcontrol.wait;" ::: "memory");
}
__device__ __forceinline__ void gdc_launch_dependents() {
    asm volatile("griddepcontrol.launch_dependents;");
}

// ---------------- fp16 mma helper -------------------------------------------
__device__ __forceinline__ void mma_f16(float* c, const uint32_t* a, const uint32_t* b) {
    asm volatile("mma.sync.aligned.m16n8k16.row.col.f32.f16.f16.f32 "
                 "{%0,%1,%2,%3}, {%4,%5,%6,%7}, {%8,%9}, {%0,%1,%2,%3};"
                 : "+f"(c[0]), "+f"(c[1]), "+f"(c[2]), "+f"(c[3])
                 : "r"(a[0]), "r"(a[1]), "r"(a[2]), "r"(a[3]),
                   "r"(b[0]), "r"(b[1]));
}

// ================ pack W1 (fp32 [512,256]) into fragment order ===============
__global__ void pack_W1(const float* __restrict__ W1) {
    gdc_launch_dependents();   // gemm1 may start its A-prologue immediately
    const int idx = blockIdx.x * blockDim.x + threadIdx.x;   // 0..32767
    if (idx >= 32 * 32 * 32) return;
    const int kt = idx >> 10;
    const int rem = idx & 1023;
    const int nt = rem >> 5;
    const int ln = rem & 31;
    const int n = nt * 8 + (ln >> 2);
    const int k = kt * 16 + (ln & 3) * 2;
    const __half2 h0 = __floats2half2_rn(W1[(size_t)k * F_HID + n],
                                         W1[(size_t)(k + 1) * F_HID + n]);
    const __half2 h1 = __floats2half2_rn(W1[(size_t)(k + 8) * F_HID + n],
                                         W1[(size_t)(k + 9) * F_HID + n]);
    g_w1f[idx * 2]     = *(const uint32_t*)&h0;
    g_w1f[idx * 2 + 1] = *(const uint32_t*)&h1;
}

// ================ pack W2 (fp32 [256,40]) into fragment order ================
__global__ void pack_W2(const float* __restrict__ W2) {
    gdc_launch_dependents();   // hist_dst is data-independent of this kernel
    const int idx = blockIdx.x * blockDim.x + threadIdx.x;   // 0..2559
    if (idx >= 16 * 5 * 32) return;
    const int kt = idx / (5 * 32);
    const int rem = idx % (5 * 32);
    const int nt = rem / 32;
    const int ln = rem % 32;
    const int n = nt * 8 + (ln >> 2);
    const int k0 = kt * 16 + (ln & 3) * 2;
    const __half2 h0 = __floats2half2_rn(W2[(size_t)k0 * F_OUT + n],
                                         W2[(size_t)(k0 + 1) * F_OUT + n]);
    const __half2 h1 = __floats2half2_rn(W2[(size_t)(k0 + 8) * F_OUT + n],
                                         W2[(size_t)(k0 + 9) * F_OUT + n]);
    g_w2f[idx * 2]     = *(const uint32_t*)&h0;
    g_w2f[idx * 2 + 1] = *(const uint32_t*)&h1;
}

// ================= gemm1: support1 = x @ W1  (fp16 MMA, fp16 out) ==========
// Block tile 64(M) x 128(N) x 32(K); 8 warps, warp tile 32x32, 3 CTAs/SM.
#define G1_BM 64
#define G1_BK 32
#define AS_PAD 36

__global__ __launch_bounds__(256, 3) void gemm1_f16(const float* __restrict__ A, int M) {
    __shared__ __align__(16) uint32_t As[2][4][8][AS_PAD];   // 9.2 KB

    const int tid  = threadIdx.x;
    const int lane = tid & 31;
    const int warp = tid >> 5;
    const int wm = warp & 1;
    const int wn = warp >> 1;
    const int rowBase = blockIdx.y * G1_BM;
    const int ntBase  = blockIdx.x * 16;

    const int ar  = tid >> 2;
    const int k0  = (tid & 3) * 8;
    const int amt = ar >> 4, arr = ar & 15;
    const int regslot = ((k0 >> 4) * 4) + (arr >> 3) + 2 * ((k0 >> 3) & 1);
    const int l0 = (arr & 7) * 4;

    float acc[2][4][4];
    #pragma unroll
    for (int mt = 0; mt < 2; mt++)
        #pragma unroll
        for (int nt = 0; nt < 4; nt++)
            #pragma unroll
            for (int r = 0; r < 4; r++) acc[mt][nt][r] = 0.f;

    const int arow = rowBase + ar;
    const float* Arow = A + (size_t)arow * F_IN + k0;
    float4 pa[2];

    {
        pa[0] = (arow < M) ? __ldcs((const float4*)(Arow))     : make_float4(0.f, 0.f, 0.f, 0.f);
        pa[1] = (arow < M) ? __ldcs((const float4*)(Arow + 4)) : make_float4(0.f, 0.f, 0.f, 0.f);
        const float* f = (const float*)pa;
        uint4 st;
        uint32_t* ps = (uint32_t*)&st;
        #pragma unroll
        for (int j = 0; j < 4; j++) {
            const __half2 h = __floats2half2_rn(f[2 * j], f[2 * j + 1]);
            ps[j] = *(const uint32_t*)&h;
        }
        *(uint4*)&As[0][amt][regslot][l0] = st;
    }
    __syncthreads();

    gdc_wait();   // g_w1f (pack_W1 output) safe to read after this

    const int NT = F_IN / G1_BK;   // 16
    for (int t = 0; t < NT; t++) {
        const int buf = t & 1;
        if (t + 1 < NT) {
            const float* Anext = Arow + (t + 1) * G1_BK;
            pa[0] = (arow < M) ? __ldcs((const float4*)(Anext))     : make_float4(0.f, 0.f, 0.f, 0.f);
            pa[1] = (arow < M) ? __ldcs((const float4*)(Anext + 4)) : make_float4(0.f, 0.f, 0.f, 0.f);
        }

        #pragma unroll
        for (int ks = 0; ks < 2; ks++) {
            const int kt = t * 2 + ks;
            uint32_t bfr[4][2];
            #pragma unroll
            for (int nt = 0; nt < 4; nt++) {
                const uint2 v = __ldg((const uint2*)
                    &g_w1f[(((size_t)kt * 32 + ntBase + wn * 4 + nt) * 32 + lane) * 2]);
                bfr[nt][0] = v.x; bfr[nt][1] = v.y;
            }
            uint32_t afr[2][4];
            #pragma unroll
            for (int mt = 0; mt < 2; mt++)
                #pragma unroll
                for (int r = 0; r < 4; r++)
                    afr[mt][r] = As[buf][wm * 2 + mt][ks * 4 + r][lane];
            #pragma unroll
            for (int mt = 0; mt < 2; mt++)
                #pragma unroll
                for (int nt = 0; nt < 4; nt++)
                    mma_f16(acc[mt][nt], afr[mt], bfr[nt]);
        }

        if (t + 1 < NT) {
            const int nb = buf ^ 1;
            const float* f = (const float*)pa;
            uint4 st;
            uint32_t* ps = (uint32_t*)&st;
            #pragma unroll
            for (int j = 0; j < 4; j++) {
                const __half2 h = __floats2half2_rn(f[2 * j], f[2 * j + 1]);
                ps[j] = *(const uint32_t*)&h;
            }
            *(uint4*)&As[nb][amt][regslot][l0] = st;
        }
        __syncthreads();
    }

    gdc_launch_dependents();   // let gather1 ramp during the epilogue/drain

    #pragma unroll
    for (int mt = 0; mt < 2; mt++) {
        const int row0 = rowBase + wm * 32 + mt * 16 + (lane >> 2);
        #pragma unroll
        for (int nt = 0; nt < 4; nt++) {
            const int col = (ntBase + wn * 4 + nt) * 8 + (lane & 3) * 2;
            if (row0 < M)
                *(__half2*)(g_s1h + (size_t)row0 * F_HID + col) =
                    __floats2half2_rn(acc[mt][nt][0], acc[mt][nt][1]);
            if (row0 + 8 < M)
                *(__half2*)(g_s1h + (size_t)(row0 + 8) * F_HID + col) =
                    __floats2half2_rn(acc[mt][nt][2], acc[mt][nt][3]);
        }
    }
}

// ================= CSR build (PDL-chained on side stream) ====================
// hist: 4 edges/thread via int4
__global__ void hist_dst(const int* __restrict__ dst, int E) {
    gdc_launch_dependents();   // scan_block gdc_waits before reading g_cnt
    const int t = blockIdx.x * blockDim.x + threadIdx.x;
    const int base = t * 4;
    if (base + 3 < E) {
        const int4 d = __ldcs((const int4*)(dst + base));
        atomicAdd(&g_cnt[d.x], 1);
        atomicAdd(&g_cnt[d.y], 1);
        atomicAdd(&g_cnt[d.z], 1);
        atomicAdd(&g_cnt[d.w], 1);
    } else {
        for (int e = base; e < E; e++)
            atomicAdd(&g_cnt[__ldcs(dst + e)], 1);
    }
}

__global__ void scan_block() {
    gdc_launch_dependents();
    gdc_wait();                // g_cnt (hist output) complete
    __shared__ int sh[SCAN_B];
    const int t = threadIdx.x;
    const int i = blockIdx.x * SCAN_B + t;
    const int v = (i < N_NODES) ? g_cnt[i] : 0;
    sh[t] = v;
    __syncthreads();
    #pragma unroll
    for (int o = 1; o < SCAN_B; o <<= 1) {
        int x = 0;
        if (t >= o) x = sh[t - o];
        __syncthreads();
        sh[t] += x;
        __syncthreads();
    }
    if (i < N_NODES) g_off[i] = sh[t] - v;
    if (t == SCAN_B - 1) g_blksum[blockIdx.x] = sh[t];
}

__global__ void scan_top() {
    gdc_launch_dependents();
    gdc_wait();
    __shared__ int sh[256];
    const int t = threadIdx.x;
    const int v = (t < SCAN_NB) ? g_blksum[t] : 0;
    sh[t] = v;
    __syncthreads();
    #pragma unroll
    for (int o = 1; o < 256; o <<= 1) {
        int x = 0;
        if (t >= o) x = sh[t - o];
        __syncthreads();
        sh[t] += x;
        __syncthreads();
    }
    if (t < SCAN_NB) g_blksum[t] = sh[t] - v;
}

// also re-zeroes g_cnt for the next graph replay and writes the sentinel
__global__ void scan_add(int E) {
    gdc_launch_dependents();
    gdc_wait();
    const int i = blockIdx.x * blockDim.x + threadIdx.x;
    if (i < N_NODES) {
        const int o = g_off[i] + g_blksum[i / SCAN_B];
        g_off[i] = o;
        g_pos[i] = o;
        g_cnt[i] = 0;
    }
    if (i == 0) g_off[N_NODES] = E;
}

// fill: 2 edges/thread
__global__ void fill_csr(const int* __restrict__ src, const int* __restrict__ dst,
                         const float* __restrict__ ew, int E) {
    gdc_wait();                // g_pos (scan_add output) complete
    const int t = blockIdx.x * blockDim.x + threadIdx.x;
    const int base = t * 2;
    if (base + 1 < E) {
        const int2   s = __ldcs((const int2*)(src + base));
        const int2   d = __ldcs((const int2*)(dst + base));
        const float2 w = __ldcs((const float2*)(ew + base));
        const int p0 = atomicAdd(&g_pos[d.x], 1);
        const int p1 = atomicAdd(&g_pos[d.y], 1);
        __stcs(&g_csr[p0], make_int2(s.x, __float_as_int(w.x)));
        __stcs(&g_csr[p1], make_int2(s.y, __float_as_int(w.y)));
    } else if (base < E) {
        const int p = atomicAdd(&g_pos[__ldcs(dst + base)], 1);
        __stcs(&g_csr[p], make_int2(__ldcs(src + base), __float_as_int(__ldcs(ew + base))));
    }
}

// ======== layer-1 gather: warp per node, full 256 feats (fp16 rows) =========
__device__ __forceinline__ void accum8(float* acc, uint4 v, float w) {
    const __half2* h = (const __half2*)&v;
    #pragma unroll
    for (int j = 0; j < 4; j++) {
        const float2 f = __half22float2(h[j]);
        acc[2 * j]     = fmaf(w, f.x, acc[2 * j]);
        acc[2 * j + 1] = fmaf(w, f.y, acc[2 * j + 1]);
    }
}

__global__ __launch_bounds__(256) void gather1(const float* __restrict__ b1) {
    gdc_launch_dependents();   // let gemm2 blocks stage W2 early
    const int n = (blockIdx.x * blockDim.x + threadIdx.x) >> 5;
    const int lane = threadIdx.x & 31;

    float acc[8];
    {
        const float4 blo = __ldg((const float4*)b1 + lane * 2);
        const float4 bhi = __ldg((const float4*)b1 + lane * 2 + 1);
        acc[0] = blo.x; acc[1] = blo.y; acc[2] = blo.z; acc[3] = blo.w;
        acc[4] = bhi.x; acc[5] = bhi.y; acc[6] = bhi.z; acc[7] = bhi.w;
    }
    gdc_wait();                // s1h (gemm1 output) safe to read after this

    const int beg = g_off[n];
    const int end = g_off[n + 1];

    int e = beg;
    for (; e + 7 < end; e += 8) {
        int2 c[8];
        uint4 v[8];
        #pragma unroll
        for (int i = 0; i < 8; i++) c[i] = __ldcs(&g_csr[e + i]);
        #pragma unroll
        for (int i = 0; i < 8; i++)
            v[i] = __ldg((const uint4*)(g_s1h + (size_t)c[i].x * F_HID) + lane);
        #pragma unroll
        for (int i = 0; i < 8; i++) accum8(acc, v[i], __int_as_float(c[i].y));
    }
    for (; e < end; e++) {
        const int2 c = __ldcs(&g_csr[e]);
        const uint4 v = __ldg((const uint4*)(g_s1h + (size_t)c.x * F_HID) + lane);
        accum8(acc, v, __int_as_float(c.y));
    }

    uint4 o;
    __half2* ph = (__half2*)&o;
    #pragma unroll
    for (int j = 0; j < 4; j++)
        ph[j] = __floats2half2_rn(fmaxf(acc[2 * j], 0.f), fmaxf(acc[2 * j + 1], 0.f));
    __stcs((uint4*)(g_h1h + (size_t)n * F_HID) + lane, o);
}

// ====== gemm2: support2 = a1 @ W2 (fp16 mma; W2 fragments via smem) =========
#define G2_NT 5
__global__ __launch_bounds__(256) void gemm2_mma() {
    __shared__ __align__(16) uint32_t Wf[16 * G2_NT * 32 * 2];   // 10 KB

    gdc_launch_dependents();   // let gather2 blocks start early

    const int tid = threadIdx.x;
    for (int i = tid; i < (16 * G2_NT * 32 * 2) / 4; i += 256)
        ((uint4*)Wf)[i] = ((const uint4*)g_w2f)[i];
    __syncthreads();

    gdc_wait();                // h1h (gather1 output) safe to read after this

    const int lane = tid & 31, warp = tid >> 5;
    const int node0 = blockIdx.x * 128 + warp * 16 + (lane >> 2);
    const int node1 = node0 + 8;
    const bool v0 = node0 < N_NODES, v1 = node1 < N_NODES;

    float acc[G2_NT][4];
    #pragma unroll
    for (int nt = 0; nt < G2_NT; nt++)
        #pragma unroll
        for (int r = 0; r < 4; r++) acc[nt][r] = 0.f;

    const __half* r0 = g_h1h + (size_t)node0 * F_HID;
    const __half* r1 = g_h1h + (size_t)node1 * F_HID;

    #pragma unroll
    for (int kt = 0; kt < 16; kt++) {
        const int kof = kt * 16 + (lane & 3) * 2;
        uint32_t a[4];
        a[0] = v0 ? __ldg((const uint32_t*)(r0 + kof))     : 0u;
        a[1] = v1 ? __ldg((const uint32_t*)(r1 + kof))     : 0u;
        a[2] = v0 ? __ldg((const uint32_t*)(r0 + kof + 8)) : 0u;
        a[3] = v1 ? __ldg((const uint32_t*)(r1 + kof + 8)) : 0u;
        #pragma unroll
        for (int nt = 0; nt < G2_NT; nt++) {
            const uint32_t* bp = &Wf[(((size_t)kt * G2_NT + nt) * 32 + lane) * 2];
            const uint32_t b[2] = {bp[0], bp[1]};
            mma_f16(acc[nt], a, b);
        }
    }

    const int col = (lane & 3) * 2;
    #pragma unroll
    for (int nt = 0; nt < G2_NT; nt++) {
        if (v0)
            *(__half2*)(g_s2h + (size_t)node0 * F_OUT + nt * 8 + col) =
                __floats2half2_rn(acc[nt][0], acc[nt][1]);
        if (v1)
            *(__half2*)(g_s2h + (size_t)node1 * F_OUT + nt * 8 + col) =
                __floats2half2_rn(acc[nt][2], acc[nt][3]);
    }
}

// ========== layer-2 gather + log_softmax: warp/node, 3 edge-slots ==========
__global__ __launch_bounds__(256) void gather2_softmax(const float* __restrict__ b2,
                                                       float* __restrict__ out) {
    const int n = (blockIdx.x * blockDim.x + threadIdx.x) >> 5;
    const int lane = threadIdx.x & 31;
    const int slot = lane / 10;
    const int pos  = lane - slot * 10;
    const bool act = lane < 30;

    const int beg = g_off[n];
    const int end = g_off[n + 1];

    float acc[4] = {0.f, 0.f, 0.f, 0.f};

    gdc_wait();                // s2h (gemm2 output) safe to read after this

    const int total = end - beg;
    int base = 0;
    for (; base + 6 <= total; base += 6) {
        const int e0 = beg + base + slot;
        const int e1 = e0 + 3;
        int2 c0, c1;
        uint2 v0, v1;
        if (act) {
            c0 = __ldcs(&g_csr[e0]);
            c1 = __ldcs(&g_csr[e1]);
            v0 = __ldg((const uint2*)(g_s2h + (size_t)c0.x * F_OUT) + pos);
            v1 = __ldg((const uint2*)(g_s2h + (size_t)c1.x * F_OUT) + pos);
            const float w0 = __int_as_float(c0.y);
            const float w1 = __int_as_float(c1.y);
            const __half2* h0 = (const __half2*)&v0;
            const __half2* h1 = (const __half2*)&v1;
            const float2 a0 = __half22float2(h0[0]), a1 = __half22float2(h0[1]);
            const float2 b0 = __half22float2(h1[0]), b1 = __half22float2(h1[1]);
            acc[0] = fmaf(w0, a0.x, acc[0]); acc[1] = fmaf(w0, a0.y, acc[1]);
            acc[2] = fmaf(w0, a1.x, acc[2]); acc[3] = fmaf(w0, a1.y, acc[3]);
            acc[0] = fmaf(w1, b0.x, acc[0]); acc[1] = fmaf(w1, b0.y, acc[1]);
            acc[2] = fmaf(w1, b1.x, acc[2]); acc[3] = fmaf(w1, b1.y, acc[3]);
        }
    }
    for (; base < total; base += 3) {
        const int e = beg + base + slot;
        if (act && e < end) {
            const int2 c = __ldcs(&g_csr[e]);
            const uint2 v = __ldg((const uint2*)(g_s2h + (size_t)c.x * F_OUT) + pos);
            const float w = __int_as_float(c.y);
            const __half2* h = (const __half2*)&v;
            const float2 f0 = __half22float2(h[0]), f1 = __half22float2(h[1]);
            acc[0] = fmaf(w, f0.x, acc[0]); acc[1] = fmaf(w, f0.y, acc[1]);
            acc[2] = fmaf(w, f1.x, acc[2]); acc[3] = fmaf(w, f1.y, acc[3]);
        }
    }

    #pragma unroll
    for (int j = 0; j < 4; j++) {
        const float a10 = __shfl_sync(0xffffffffu, acc[j], pos + 10);
        const float a20 = __shfl_sync(0xffffffffu, acc[j], pos + 20);
        acc[j] += a10 + a20;
    }

    const bool own = lane < 10;
    if (own) {
        const float4 b = __ldg((const float4*)b2 + lane);
        acc[0] += b.x; acc[1] += b.y; acc[2] += b.z; acc[3] += b.w;
    }

    const float NEG_INF = __int_as_float(0xff800000);
    float m = own ? fmaxf(fmaxf(acc[0], acc[1]), fmaxf(acc[2], acc[3])) : NEG_INF;
    #pragma unroll
    for (int o = 16; o > 0; o >>= 1)
        m = fmaxf(m, __shfl_xor_sync(0xffffffffu, m, o));
    float s = own ? (expf(acc[0] - m) + expf(acc[1] - m) +
                     expf(acc[2] - m) + expf(acc[3] - m)) : 0.f;
    #pragma unroll
    for (int o = 16; o > 0; o >>= 1)
        s += __shfl_xor_sync(0xffffffffu, s, o);
    const float l = m + logf(s);

    if (own) {
        const float4 o4 = make_float4(acc[0] - l, acc[1] - l, acc[2] - l, acc[3] - l);
        *((float4*)(out + (size_t)n * F_OUT) + lane) = o4;
    }
}

// ---------------- launch ----------------------------------------------------
template <typename... Args>
static void launch_pdl_s(cudaStream_t st, void (*k)(Args...), dim3 grid, dim3 block,
                         Args... args) {
    cudaLaunchConfig_t cfg = {};
    cfg.gridDim = grid; cfg.blockDim = block; cfg.stream = st;
    cudaLaunchAttribute attr[1];
    attr[0].id = cudaLaunchAttributeProgrammaticStreamSerialization;
    attr[0].val.programmaticStreamSerializationAllowed = 1;
    cfg.attrs = attr; cfg.numAttrs = 1;
    cudaLaunchKernelEx(&cfg, k, args...);
}

extern "C" void kernel_launch(void* const* d_in, const int* in_sizes, int n_in,
                              void* d_out, int out_size) {
    const float* x   = (const float*)d_in[0];
    const int*   ei  = (const int*)d_in[1];
    const float* ew  = (const float*)d_in[2];
    const float* W1  = (const float*)d_in[3];
    const float* b1  = (const float*)d_in[4];
    const float* W2  = (const float*)d_in[5];
    const float* b2  = (const float*)d_in[6];
    float* out = (float*)d_out;

    const int E = in_sizes[2];
    const int* src = ei;
    const int* dst = ei + E;

    // Fork: CSR build + W2 pack run concurrently with W1 pack + gemm1.
    cudaStream_t s2;
    cudaStreamCreate(&s2);
    cudaEvent_t evFork, evJoin;
    cudaEventCreateWithFlags(&evFork, cudaEventDisableTiming);
    cudaEventCreateWithFlags(&evJoin, cudaEventDisableTiming);

    cudaEventRecord(evFork, 0);
    cudaStreamWaitEvent(s2, evFork, 0);

    // branch A (main stream): pack W1, then support1 = x @ W1 (PDL-chained)
    pack_W1<<<128, 256>>>(W1);
    launch_pdl_s(cudaStream_t(0), gemm1_f16,
                 dim3(2, (N_NODES + G1_BM - 1) / G1_BM), dim3(256), x, (int)N_NODES);

    // branch B (side stream): W2 pack + CSR build, PDL-chained throughout
    {
        const int nb = (N_NODES + 255) / 256;
        pack_W2<<<10, 256, 0, s2>>>(W2);
        launch_pdl_s(s2, hist_dst, dim3((E / 4 + 255) / 256 + 1), dim3(256), dst, E);
        launch_pdl_s(s2, scan_block, dim3(SCAN_NB), dim3(SCAN_B));
        launch_pdl_s(s2, scan_top, dim3(1), dim3(256));
        launch_pdl_s(s2, scan_add, dim3(nb), dim3(256), E);
        launch_pdl_s(s2, fill_csr, dim3((E / 2 + 255) / 256 + 1), dim3(256),
                     src, dst, ew, E);
    }

    cudaEventRecord(evJoin, s2);
    cudaStreamWaitEvent(0, evJoin, 0);

    // layer-1 gather (PDL: prologue + ramp overlap gemm1 epilogue/drain)
    launch_pdl_s(cudaStream_t(0), gather1, dim3((N_NODES * 32 + 255) / 256), dim3(256), b1);
    // support2 = a1 @ W2 (PDL: W2 smem staging overlaps gather1 straggler drain)
    launch_pdl_s(cudaStream_t(0), gemm2_mma, dim3((N_NODES + 127) / 128), dim3(256));
    // out = log_softmax(b2 + gather(ew * support2[src])) (PDL: overlaps gemm2 drain)
    launch_pdl_s(cudaStream_t(0), gather2_softmax,
                 dim3((N_NODES * 32 + 255) / 256), dim3(256), b2, out);

    cudaStreamDestroy(s2);
    cudaEventDestroy(evFork);
    cudaEventDestroy(evJoin);
}